// round 3
// baseline (speedup 1.0000x reference)
#include <cuda_runtime.h>
#include <cuda_bf16.h>
#include <math.h>

// ---------------- problem constants ----------------
#define BB   4
#define TT   4096
#define BT   (BB*TT)      // 16384 tokens
#define HID  2048
#define ED   256          // engram dim
#define NH   8            // total hash heads
#define HD   32           // head dim
#define KW   4            // conv kernel
#define DILN 3            // dilation
#define PADL 9            // causal left pad

// ---------------- scratch (device globals; no allocation) ----------------
__device__ float gE [(size_t)BT * ED];    // e' after conv/ln/silu      (16 MB)
__device__ float gKP[(size_t)BT * HID];   // key pre-LN                 (134 MB)
__device__ float gM [(size_t)HID * ED];   // M = Wo @ Wv                (2 MB)
__device__ float gG [BT];                 // per-token gate

// ---------------- packed f32x2 helpers (Blackwell) ----------------
typedef unsigned long long ull;

__device__ __forceinline__ ull pk2(float lo, float hi) {
    ull r; asm("mov.b64 %0, {%1, %2};" : "=l"(r) : "f"(lo), "f"(hi)); return r;
}
__device__ __forceinline__ void upk2(ull v, float& lo, float& hi) {
    asm("mov.b64 {%0, %1}, %2;" : "=f"(lo), "=f"(hi) : "l"(v));
}
__device__ __forceinline__ void fma2(ull& d, ull a, ull b) {
    asm("fma.rn.f32x2 %0, %1, %2, %0;" : "+l"(d) : "l"(a), "l"(b));
}

// =====================================================================
// Kernel 0: gM[e,c] = sum_d Wo[e,d] * Wv[d,c]
//   Wo: (2048 x 2048) row-major (d contiguous)  -> A, K-contiguous
//   Wv: (2048 x 256)  row-major (c contiguous)  -> B, N-contiguous
//   Tile 64x64, BK=16, 256 threads, 4x4 per thread, f32x2 packed.
// =====================================================================
__global__ __launch_bounds__(256) void k_matM(const float* __restrict__ Wo,
                                              const float* __restrict__ Wv) {
    const int BM = 64, BN = 64, BK = 16, KT = 2048, NC = 256;
    __shared__ float As[BK][BM + 4];
    __shared__ float Bs[BK][BN + 4];

    int bm = blockIdx.y * BM;          // e tile
    int bn = blockIdx.x * BN;          // c tile
    int tid = threadIdx.x;
    int tx = tid & 15, ty = tid >> 4;
    int m0 = ty * 4, n0 = tx * 4;

    ull acc[2][4];
#pragma unroll
    for (int i = 0; i < 2; i++)
#pragma unroll
        for (int j = 0; j < 4; j++) acc[i][j] = 0ull;

    for (int kt = 0; kt < KT; kt += BK) {
        // A tile: 64 rows x 16 k = 256 float4, one per thread
        {
            int m = tid >> 2, kq = tid & 3;
            float4 v = *(const float4*)(Wo + (size_t)(bm + m) * KT + kt + kq * 4);
            As[kq * 4 + 0][m] = v.x; As[kq * 4 + 1][m] = v.y;
            As[kq * 4 + 2][m] = v.z; As[kq * 4 + 3][m] = v.w;
        }
        // B tile: 16 k-rows x 64 n = 256 float4, [k][n] direct
        {
            int kk = tid >> 4, nq = tid & 15;
            float4 v = *(const float4*)(Wv + (size_t)(kt + kk) * NC + bn + nq * 4);
            *(float4*)&Bs[kk][nq * 4] = v;
        }
        __syncthreads();
#pragma unroll
        for (int k = 0; k < BK; k++) {
            ull a2[2];
#pragma unroll
            for (int ip = 0; ip < 2; ip++) a2[ip] = *(const ull*)&As[k][m0 + 2 * ip];
            float4 b = *(const float4*)&Bs[k][n0];
            ull b2[4] = { pk2(b.x, b.x), pk2(b.y, b.y), pk2(b.z, b.z), pk2(b.w, b.w) };
#pragma unroll
            for (int ip = 0; ip < 2; ip++)
#pragma unroll
                for (int j = 0; j < 4; j++) fma2(acc[ip][j], a2[ip], b2[j]);
        }
        __syncthreads();
    }
#pragma unroll
    for (int ip = 0; ip < 2; ip++) {
        int r0 = bm + m0 + 2 * ip;
        float lo[4], hi[4];
#pragma unroll
        for (int j = 0; j < 4; j++) upk2(acc[ip][j], lo[j], hi[j]);
        *(float4*)(gM + (size_t)r0 * NC + bn + n0)       = make_float4(lo[0], lo[1], lo[2], lo[3]);
        *(float4*)(gM + (size_t)(r0 + 1) * NC + bn + n0) = make_float4(hi[0], hi[1], hi[2], hi[3]);
    }
}

// =====================================================================
// Kernel 1: hash-gather + causal dilated depthwise conv + LN + SiLU -> gE
//   One block = 32 tokens of one batch row (+9-token halo in smem).
//   256 threads: gather phase thread==channel; conv phase warp==token.
// =====================================================================
__global__ __launch_bounds__(256) void k_embed(const int* __restrict__ hashes,
                                               const int* __restrict__ offs,
                                               const float* __restrict__ emb,
                                               const float* __restrict__ cw,
                                               const float* __restrict__ lg,
                                               const float* __restrict__ lb) {
    const int TB = 32, HALO = PADL;
    __shared__ float se[(TB + HALO) * ED];   // 41 KB
    __shared__ float swt[KW * ED];           // conv weights transposed [k][ch]
    __shared__ float sg[ED], sb[ED];

    int tid = threadIdx.x;
    int b = blockIdx.y, t0 = blockIdx.x * TB;

    sg[tid] = lg[tid];
    sb[tid] = lb[tid];
#pragma unroll
    for (int k = 0; k < KW; k++) swt[k * ED + tid] = cw[tid * KW + k];

    // gather: channel = tid, token = lt
    int h = tid >> 5, d = tid & 31;
    int off_h = offs[h];
    for (int lt = 0; lt < TB + HALO; lt++) {
        int t = t0 - HALO + lt;
        float v = 0.f;
        if (t >= 0) {
            int row = hashes[(b * TT + t) * NH + h] + off_h;
            v = emb[(size_t)row * HD + d];
        }
        se[lt * ED + tid] = v;
    }
    __syncthreads();

    int wid = tid >> 5, lane = tid & 31;
    for (int it = 0; it < TB / 8; it++) {
        int tok = it * 8 + wid;
        int lt = tok + HALO;
        float c[8], ev[8];
        float s = 0.f, q = 0.f;
#pragma unroll
        for (int j = 0; j < 8; j++) {
            int ch = lane + 32 * j;
            float a = 0.f;
#pragma unroll
            for (int k = 0; k < KW; k++)
                a += se[(lt - PADL + k * DILN) * ED + ch] * swt[k * ED + ch];
            c[j] = a;
            ev[j] = se[lt * ED + ch];
            s += a; q += a * a;
        }
#pragma unroll
        for (int o = 16; o; o >>= 1) {
            s += __shfl_xor_sync(0xffffffffu, s, o);
            q += __shfl_xor_sync(0xffffffffu, q, o);
        }
        float mean = s * (1.f / ED);
        float var  = q * (1.f / ED) - mean * mean;
        float rstd = rsqrtf(var + 1e-5f);
#pragma unroll
        for (int j = 0; j < 8; j++) {
            int ch = lane + 32 * j;
            float y = (c[j] - mean) * rstd * sg[ch] + sb[ch];
            float o = ev[j] + y * (1.f / (1.f + expf(-y)));
            gE[(size_t)(b * TT + t0 + tok) * ED + ch] = o;
        }
    }
}

// =====================================================================
// Kernel 2/4: GEMM NT  C[M x 2048] = gE[M x 256] * B[2048 x 256]^T
//   MODE 0: B = Wk (param), C = gKP
//   MODE 1: B = gM,        C = Cout, scaled by gG[row]
//   128x128 tile, BK=16, 256 threads, 8x8 per thread, f32x2 (row-pair pack)
// =====================================================================
template <int MODE>
__global__ __launch_bounds__(256, 2) void k_gemm_nt(const float* __restrict__ Bparam,
                                                    float* __restrict__ Cout) {
    const int BM = 128, BN = 128, BK = 16, KT = ED;
    __shared__ float As[BK][BM + 4];
    __shared__ float Bs[BK][BN + 4];

    const float* A  = gE;
    const float* Bp = (MODE == 0) ? Bparam : (const float*)gM;
    float*       Cp = (MODE == 0) ? (float*)gKP : Cout;

    int bm = blockIdx.y * BM, bn = blockIdx.x * BN;
    int tid = threadIdx.x;
    int tx = tid & 15, ty = tid >> 4;
    int m0 = ty * 8, n0 = tx * 8;

    ull acc[4][8];
#pragma unroll
    for (int i = 0; i < 4; i++)
#pragma unroll
        for (int j = 0; j < 8; j++) acc[i][j] = 0ull;

    for (int kt = 0; kt < KT; kt += BK) {
#pragma unroll
        for (int it = 0; it < 2; it++) {
            int idx = tid * 2 + it;
            int m = idx >> 2, kq = idx & 3;
            float4 v = *(const float4*)(A + (size_t)(bm + m) * KT + kt + kq * 4);
            As[kq * 4 + 0][m] = v.x; As[kq * 4 + 1][m] = v.y;
            As[kq * 4 + 2][m] = v.z; As[kq * 4 + 3][m] = v.w;
            float4 w = *(const float4*)(Bp + (size_t)(bn + m) * KT + kt + kq * 4);
            Bs[kq * 4 + 0][m] = w.x; Bs[kq * 4 + 1][m] = w.y;
            Bs[kq * 4 + 2][m] = w.z; Bs[kq * 4 + 3][m] = w.w;
        }
        __syncthreads();
#pragma unroll
        for (int k = 0; k < BK; k++) {
            ull a2[4];
#pragma unroll
            for (int ip = 0; ip < 4; ip++) a2[ip] = *(const ull*)&As[k][m0 + 2 * ip];
            float4 b0 = *(const float4*)&Bs[k][n0];
            float4 b1 = *(const float4*)&Bs[k][n0 + 4];
            ull b2[8] = { pk2(b0.x, b0.x), pk2(b0.y, b0.y), pk2(b0.z, b0.z), pk2(b0.w, b0.w),
                          pk2(b1.x, b1.x), pk2(b1.y, b1.y), pk2(b1.z, b1.z), pk2(b1.w, b1.w) };
#pragma unroll
            for (int ip = 0; ip < 4; ip++)
#pragma unroll
                for (int j = 0; j < 8; j++) fma2(acc[ip][j], a2[ip], b2[j]);
        }
        __syncthreads();
    }

#pragma unroll
    for (int ip = 0; ip < 4; ip++) {
        int r0 = bm + m0 + 2 * ip;
        float slo = 1.f, shi = 1.f;
        if (MODE == 1) { slo = gG[r0]; shi = gG[r0 + 1]; }
        float lo[8], hi[8];
#pragma unroll
        for (int j = 0; j < 8; j++) {
            upk2(acc[ip][j], lo[j], hi[j]);
            lo[j] *= slo; hi[j] *= shi;
        }
        float* c0 = Cp + (size_t)r0 * HID + bn + n0;
        float* c1 = Cp + (size_t)(r0 + 1) * HID + bn + n0;
        *(float4*)(c0)     = make_float4(lo[0], lo[1], lo[2], lo[3]);
        *(float4*)(c0 + 4) = make_float4(lo[4], lo[5], lo[6], lo[7]);
        *(float4*)(c1)     = make_float4(hi[0], hi[1], hi[2], hi[3]);
        *(float4*)(c1 + 4) = make_float4(hi[4], hi[5], hi[6], hi[7]);
    }
}

// =====================================================================
// Kernel 3: per-token gate
//   key = LN(gKP row), query = LN(x row); g = sigmoid(signed-sqrt(dot/sqrt(D)))
//   One block (256 thr) per token; each thread owns 8 coalesced dims.
// =====================================================================
__global__ __launch_bounds__(256) void k_gate(const float* __restrict__ x,
                                              const float* __restrict__ lkg,
                                              const float* __restrict__ lkb,
                                              const float* __restrict__ lqg,
                                              const float* __restrict__ lqb) {
    int t = blockIdx.x, tid = threadIdx.x;
    float kp[8], xv[8];
    float s1k = 0.f, s2k = 0.f, s1x = 0.f, s2x = 0.f;
#pragma unroll
    for (int j = 0; j < 8; j++) {
        int dd = tid + 256 * j;
        kp[j] = gKP[(size_t)t * HID + dd];
        xv[j] = x  [(size_t)t * HID + dd];
        s1k += kp[j]; s2k += kp[j] * kp[j];
        s1x += xv[j]; s2x += xv[j] * xv[j];
    }
#pragma unroll
    for (int o = 16; o; o >>= 1) {
        s1k += __shfl_xor_sync(0xffffffffu, s1k, o);
        s2k += __shfl_xor_sync(0xffffffffu, s2k, o);
        s1x += __shfl_xor_sync(0xffffffffu, s1x, o);
        s2x += __shfl_xor_sync(0xffffffffu, s2x, o);
    }
    __shared__ float red[4][8];
    __shared__ float fin[4];
    int wid = tid >> 5, lane = tid & 31;
    if (lane == 0) { red[0][wid] = s1k; red[1][wid] = s2k; red[2][wid] = s1x; red[3][wid] = s2x; }
    __syncthreads();
    if (tid < 4) {
        float s = 0.f;
#pragma unroll
        for (int w = 0; w < 8; w++) s += red[tid][w];
        fin[tid] = s;
    }
    __syncthreads();
    float mk = fin[0] * (1.f / HID), mx = fin[2] * (1.f / HID);
    float rk = rsqrtf(fin[1] * (1.f / HID) - mk * mk + 1e-5f);
    float rx = rsqrtf(fin[3] * (1.f / HID) - mx * mx + 1e-5f);

    float dacc = 0.f;
#pragma unroll
    for (int j = 0; j < 8; j++) {
        int dd = tid + 256 * j;
        float ky = (kp[j] - mk) * rk * lkg[dd] + lkb[dd];
        float qy = (xv[j] - mx) * rx * lqg[dd] + lqb[dd];
        dacc += ky * qy;
    }
#pragma unroll
    for (int o = 16; o; o >>= 1) dacc += __shfl_xor_sync(0xffffffffu, dacc, o);
    __syncthreads();
    if (lane == 0) red[0][wid] = dacc;
    __syncthreads();
    if (tid == 0) {
        float s = 0.f;
#pragma unroll
        for (int w = 0; w < 8; w++) s += red[0][w];
        s *= rsqrtf((float)HID);                 // / sqrt(D)
        float a = fmaxf(fabsf(s), 1e-6f);
        float sgn = (s > 0.f) ? 1.f : ((s < 0.f) ? -1.f : 0.f);
        float z = sqrtf(a) * sgn;
        gG[t] = 1.f / (1.f + expf(-z));
    }
}

// =====================================================================
extern "C" void kernel_launch(void* const* d_in, const int* in_sizes, int n_in,
                              void* d_out, int out_size) {
    const float* x      = (const float*)d_in[0];
    const int*   hashes = (const int*)  d_in[1];
    const int*   offs   = (const int*)  d_in[2];
    const float* emb    = (const float*)d_in[3];
    const float* convw  = (const float*)d_in[4];
    const float* lncg   = (const float*)d_in[5];
    const float* lncb   = (const float*)d_in[6];
    const float* Wk     = (const float*)d_in[7];
    const float* Wv     = (const float*)d_in[8];
    const float* Wo     = (const float*)d_in[9];
    const float* lkg    = (const float*)d_in[10];
    const float* lkb    = (const float*)d_in[11];
    const float* lqg    = (const float*)d_in[12];
    const float* lqb    = (const float*)d_in[13];
    float* out = (float*)d_out;

    // 0) M = Wo @ Wv   (folds the 2048x2048 output projection into 2048x256)
    k_matM<<<dim3(ED / 64, HID / 64), 256>>>(Wo, Wv);

    // 1) gather + conv + LN + SiLU -> gE
    k_embed<<<dim3(TT / 32, BB), 256>>>(hashes, offs, emb, convw, lncg, lncb);

    // 2) gKP = gE @ Wk^T
    k_gemm_nt<0><<<dim3(HID / 128, BT / 128), 256>>>(Wk, nullptr);

    // 3) gate
    k_gate<<<BT, 256>>>(x, lkg, lkb, lqg, lqb);

    // 4) out = diag(g) * (gE @ M^T)
    k_gemm_nt<1><<<dim3(HID / 128, BT / 128), 256>>>(nullptr, out);
}

// round 4
// speedup vs baseline: 2.2651x; 2.2651x over previous
#include <cuda_runtime.h>
#include <cuda_bf16.h>
#include <math.h>
#include <stdint.h>

// ---------------- problem constants ----------------
#define BB   4
#define TT   4096
#define BT   (BB*TT)      // 16384 tokens
#define HID  2048
#define ED   256          // engram dim
#define NH   8            // total hash heads
#define HD   32           // head dim
#define KW   4            // conv kernel
#define DILN 3            // dilation
#define PADL 9            // causal left pad

// ---------------- scratch (device globals; no allocation) ----------------
__device__ float gE [(size_t)BT * ED];    // e' after conv/ln/silu      (16 MB)
__device__ float gKP[(size_t)BT * HID];   // key pre-LN                 (134 MB)
__device__ float gM [(size_t)HID * ED];   // M = Wo @ Wv                (2 MB)
__device__ float gG [BT];                 // per-token gate

// ---------------- packed f32x2 helpers (for exact-fp32 k_matM) ----------
typedef unsigned long long ull;

__device__ __forceinline__ ull pk2(float lo, float hi) {
    ull r; asm("mov.b64 %0, {%1, %2};" : "=l"(r) : "f"(lo), "f"(hi)); return r;
}
__device__ __forceinline__ void upk2(ull v, float& lo, float& hi) {
    asm("mov.b64 {%0, %1}, %2;" : "=f"(lo), "=f"(hi) : "l"(v));
}
__device__ __forceinline__ void fma2(ull& d, ull a, ull b) {
    asm("fma.rn.f32x2 %0, %1, %2, %0;" : "+l"(d) : "l"(a), "l"(b));
}

// ---------------- tf32 / ldmatrix / mma helpers -------------------------
__device__ __forceinline__ uint32_t f2tf32(float f) {
    uint32_t u; asm("cvt.rna.tf32.f32 %0, %1;" : "=r"(u) : "f"(f)); return u;
}
__device__ __forceinline__ uint32_t smem_u32(const void* p) {
    uint32_t r;
    asm("{ .reg .u64 t; cvta.to.shared.u64 t, %1; cvt.u32.u64 %0, t; }" : "=r"(r) : "l"(p));
    return r;
}
__device__ __forceinline__ void ldsm4(uint32_t& r0, uint32_t& r1, uint32_t& r2, uint32_t& r3,
                                      uint32_t addr) {
    asm volatile("ldmatrix.sync.aligned.m8n8.x4.shared.b16 {%0,%1,%2,%3}, [%4];"
                 : "=r"(r0), "=r"(r1), "=r"(r2), "=r"(r3) : "r"(addr));
}
__device__ __forceinline__ void mma_tf32(float* c, const uint32_t* a, uint32_t b0, uint32_t b1) {
    asm volatile("mma.sync.aligned.m16n8k8.row.col.f32.tf32.tf32.f32 "
                 "{%0,%1,%2,%3}, {%4,%5,%6,%7}, {%8,%9}, {%0,%1,%2,%3};"
                 : "+f"(c[0]), "+f"(c[1]), "+f"(c[2]), "+f"(c[3])
                 : "r"(a[0]), "r"(a[1]), "r"(a[2]), "r"(a[3]), "r"(b0), "r"(b1));
}

// =====================================================================
// Kernel 0: gM[e,c] = sum_d Wo[e,d] * Wv[d,c]   (kept exact fp32)
// =====================================================================
__global__ __launch_bounds__(256) void k_matM(const float* __restrict__ Wo,
                                              const float* __restrict__ Wv) {
    const int BM = 64, BN = 64, BK = 16, KT = 2048, NC = 256;
    __shared__ float As[BK][BM + 4];
    __shared__ float Bs[BK][BN + 4];

    int bm = blockIdx.y * BM;
    int bn = blockIdx.x * BN;
    int tid = threadIdx.x;
    int tx = tid & 15, ty = tid >> 4;
    int m0 = ty * 4, n0 = tx * 4;

    ull acc[2][4];
#pragma unroll
    for (int i = 0; i < 2; i++)
#pragma unroll
        for (int j = 0; j < 4; j++) acc[i][j] = 0ull;

    for (int kt = 0; kt < KT; kt += BK) {
        {
            int m = tid >> 2, kq = tid & 3;
            float4 v = *(const float4*)(Wo + (size_t)(bm + m) * KT + kt + kq * 4);
            As[kq * 4 + 0][m] = v.x; As[kq * 4 + 1][m] = v.y;
            As[kq * 4 + 2][m] = v.z; As[kq * 4 + 3][m] = v.w;
        }
        {
            int kk = tid >> 4, nq = tid & 15;
            float4 v = *(const float4*)(Wv + (size_t)(kt + kk) * NC + bn + nq * 4);
            *(float4*)&Bs[kk][nq * 4] = v;
        }
        __syncthreads();
#pragma unroll
        for (int k = 0; k < BK; k++) {
            ull a2[2];
#pragma unroll
            for (int ip = 0; ip < 2; ip++) a2[ip] = *(const ull*)&As[k][m0 + 2 * ip];
            float4 b = *(const float4*)&Bs[k][n0];
            ull b2[4] = { pk2(b.x, b.x), pk2(b.y, b.y), pk2(b.z, b.z), pk2(b.w, b.w) };
#pragma unroll
            for (int ip = 0; ip < 2; ip++)
#pragma unroll
                for (int j = 0; j < 4; j++) fma2(acc[ip][j], a2[ip], b2[j]);
        }
        __syncthreads();
    }
#pragma unroll
    for (int ip = 0; ip < 2; ip++) {
        int r0 = bm + m0 + 2 * ip;
        float lo[4], hi[4];
#pragma unroll
        for (int j = 0; j < 4; j++) upk2(acc[ip][j], lo[j], hi[j]);
        *(float4*)(gM + (size_t)r0 * NC + bn + n0)       = make_float4(lo[0], lo[1], lo[2], lo[3]);
        *(float4*)(gM + (size_t)(r0 + 1) * NC + bn + n0) = make_float4(hi[0], hi[1], hi[2], hi[3]);
    }
}

// =====================================================================
// Kernel 1: hash-gather + causal dilated depthwise conv + LN + SiLU -> gE
// =====================================================================
__global__ __launch_bounds__(256) void k_embed(const int* __restrict__ hashes,
                                               const int* __restrict__ offs,
                                               const float* __restrict__ emb,
                                               const float* __restrict__ cw,
                                               const float* __restrict__ lg,
                                               const float* __restrict__ lb) {
    const int TB = 32, HALO = PADL;
    __shared__ float se[(TB + HALO) * ED];
    __shared__ float swt[KW * ED];
    __shared__ float sg[ED], sb[ED];

    int tid = threadIdx.x;
    int b = blockIdx.y, t0 = blockIdx.x * TB;

    sg[tid] = lg[tid];
    sb[tid] = lb[tid];
#pragma unroll
    for (int k = 0; k < KW; k++) swt[k * ED + tid] = cw[tid * KW + k];

    int h = tid >> 5, d = tid & 31;
    int off_h = offs[h];
    for (int lt = 0; lt < TB + HALO; lt++) {
        int t = t0 - HALO + lt;
        float v = 0.f;
        if (t >= 0) {
            int row = hashes[(b * TT + t) * NH + h] + off_h;
            v = emb[(size_t)row * HD + d];
        }
        se[lt * ED + tid] = v;
    }
    __syncthreads();

    int wid = tid >> 5, lane = tid & 31;
    for (int it = 0; it < TB / 8; it++) {
        int tok = it * 8 + wid;
        int lt = tok + HALO;
        float c[8], ev[8];
        float s = 0.f, q = 0.f;
#pragma unroll
        for (int j = 0; j < 8; j++) {
            int ch = lane + 32 * j;
            float a = 0.f;
#pragma unroll
            for (int k = 0; k < KW; k++)
                a += se[(lt - PADL + k * DILN) * ED + ch] * swt[k * ED + ch];
            c[j] = a;
            ev[j] = se[lt * ED + ch];
            s += a; q += a * a;
        }
#pragma unroll
        for (int o = 16; o; o >>= 1) {
            s += __shfl_xor_sync(0xffffffffu, s, o);
            q += __shfl_xor_sync(0xffffffffu, q, o);
        }
        float mean = s * (1.f / ED);
        float var  = q * (1.f / ED) - mean * mean;
        float rstd = rsqrtf(var + 1e-5f);
#pragma unroll
        for (int j = 0; j < 8; j++) {
            int ch = lane + 32 * j;
            float y = (c[j] - mean) * rstd * sg[ch] + sb[ch];
            float o = ev[j] + y * (1.f / (1.f + expf(-y)));
            gE[(size_t)(b * TT + t0 + tok) * ED + ch] = o;
        }
    }
}

// =====================================================================
// Kernel 2/4: tensor-core GEMM NT  C[BT x 2048] = gE[BT x 256] * B[2048 x 256]^T
//   tf32 mma.sync m16n8k8, fp32 accumulate.
//   MODE 0: B = Wk, C = gKP.   MODE 1: B = gM, C = Cout scaled by gG[row].
//   Block 128x128, BK=32, 8 warps (2m x 4n), warp tile 64x32.
// =====================================================================
template <int MODE>
__global__ __launch_bounds__(256, 2) void k_gemm_tc(const float* __restrict__ Bparam,
                                                    float* __restrict__ Cout) {
    const int BM = 128, BN = 128, BK = 32, LDS = 36;   // 36-float row stride: ldmatrix conflict-free
    __shared__ uint32_t As[BM * LDS];
    __shared__ uint32_t Bs[BN * LDS];

    const float* A  = gE;
    const float* Bp = (MODE == 0) ? Bparam : (const float*)gM;
    float*       Cp = (MODE == 0) ? (float*)gKP : Cout;

    int bm = blockIdx.y * BM, bn = blockIdx.x * BN;
    int tid = threadIdx.x, lane = tid & 31, wid = tid >> 5;
    int wm = wid & 1;        // 2 warp-rows of 64
    int wn = wid >> 1;       // 4 warp-cols of 32

    float acc[4][4][4];
#pragma unroll
    for (int mt = 0; mt < 4; mt++)
#pragma unroll
        for (int nt = 0; nt < 4; nt++)
#pragma unroll
            for (int r = 0; r < 4; r++) acc[mt][nt][r] = 0.f;

    // ldmatrix lane base addresses (bytes, shared space)
    // A fragment (16x8 tf32): matrices [rows0-7,k0-3][rows8-15,k0-3][rows0-7,k4-7][rows8-15,k4-7]
    uint32_t a_base = smem_u32(As) +
        (((wm * 64 + (lane & 15)) * LDS + ((lane >> 4) * 4)) << 2);
    // B fragment pairs: [tile0 k0-3][tile0 k4-7][tile1 k0-3][tile1 k4-7]
    uint32_t b_base = smem_u32(Bs) +
        (((wn * 32 + (lane >> 4) * 8 + (lane & 7)) * LDS + (((lane >> 3) & 1) * 4)) << 2);

    for (int kt = 0; kt < ED; kt += BK) {
#pragma unroll
        for (int i = 0; i < 4; i++) {
            int idx = tid + 256 * i;
            int row = idx >> 3, q = idx & 7;
            float4 v = *(const float4*)(A + (size_t)(bm + row) * ED + kt + q * 4);
            uint32_t* da = &As[row * LDS + q * 4];
            da[0] = f2tf32(v.x); da[1] = f2tf32(v.y); da[2] = f2tf32(v.z); da[3] = f2tf32(v.w);
            float4 w = *(const float4*)(Bp + (size_t)(bn + row) * ED + kt + q * 4);
            uint32_t* db = &Bs[row * LDS + q * 4];
            db[0] = f2tf32(w.x); db[1] = f2tf32(w.y); db[2] = f2tf32(w.z); db[3] = f2tf32(w.w);
        }
        __syncthreads();
#pragma unroll
        for (int ks = 0; ks < 4; ks++) {
            uint32_t a[4][4], b[2][4];
#pragma unroll
            for (int mt = 0; mt < 4; mt++)
                ldsm4(a[mt][0], a[mt][1], a[mt][2], a[mt][3],
                      a_base + ((mt * 16 * LDS + ks * 8) << 2));
#pragma unroll
            for (int p = 0; p < 2; p++)
                ldsm4(b[p][0], b[p][1], b[p][2], b[p][3],
                      b_base + ((p * 16 * LDS + ks * 8) << 2));
#pragma unroll
            for (int mt = 0; mt < 4; mt++)
#pragma unroll
                for (int nt = 0; nt < 4; nt++) {
                    int p = nt >> 1, s = (nt & 1) * 2;
                    mma_tf32(acc[mt][nt], a[mt], b[p][s], b[p][s + 1]);
                }
        }
        __syncthreads();
    }

    // epilogue: c0,c1 -> row lane>>2, cols 2*(lane&3)+{0,1}; c2,c3 -> row+8
#pragma unroll
    for (int mt = 0; mt < 4; mt++) {
        int r0 = bm + wm * 64 + mt * 16 + (lane >> 2);
        float s0 = 1.f, s1 = 1.f;
        if (MODE == 1) { s0 = gG[r0]; s1 = gG[r0 + 8]; }
#pragma unroll
        for (int nt = 0; nt < 4; nt++) {
            int c0 = bn + wn * 32 + nt * 8 + (lane & 3) * 2;
            float2 v0 = make_float2(acc[mt][nt][0] * s0, acc[mt][nt][1] * s0);
            float2 v1 = make_float2(acc[mt][nt][2] * s1, acc[mt][nt][3] * s1);
            *(float2*)(Cp + (size_t)r0 * HID + c0)       = v0;
            *(float2*)(Cp + (size_t)(r0 + 8) * HID + c0) = v1;
        }
    }
}

// =====================================================================
// Kernel 3: per-token gate
// =====================================================================
__global__ __launch_bounds__(256) void k_gate(const float* __restrict__ x,
                                              const float* __restrict__ lkg,
                                              const float* __restrict__ lkb,
                                              const float* __restrict__ lqg,
                                              const float* __restrict__ lqb) {
    int t = blockIdx.x, tid = threadIdx.x;
    float kp[8], xv[8];
    float s1k = 0.f, s2k = 0.f, s1x = 0.f, s2x = 0.f;
#pragma unroll
    for (int j = 0; j < 8; j++) {
        int dd = tid + 256 * j;
        kp[j] = gKP[(size_t)t * HID + dd];
        xv[j] = x  [(size_t)t * HID + dd];
        s1k += kp[j]; s2k += kp[j] * kp[j];
        s1x += xv[j]; s2x += xv[j] * xv[j];
    }
#pragma unroll
    for (int o = 16; o; o >>= 1) {
        s1k += __shfl_xor_sync(0xffffffffu, s1k, o);
        s2k += __shfl_xor_sync(0xffffffffu, s2k, o);
        s1x += __shfl_xor_sync(0xffffffffu, s1x, o);
        s2x += __shfl_xor_sync(0xffffffffu, s2x, o);
    }
    __shared__ float red[4][8];
    __shared__ float fin[4];
    int wid = tid >> 5, lane = tid & 31;
    if (lane == 0) { red[0][wid] = s1k; red[1][wid] = s2k; red[2][wid] = s1x; red[3][wid] = s2x; }
    __syncthreads();
    if (tid < 4) {
        float s = 0.f;
#pragma unroll
        for (int w = 0; w < 8; w++) s += red[tid][w];
        fin[tid] = s;
    }
    __syncthreads();
    float mk = fin[0] * (1.f / HID), mx = fin[2] * (1.f / HID);
    float rk = rsqrtf(fin[1] * (1.f / HID) - mk * mk + 1e-5f);
    float rx = rsqrtf(fin[3] * (1.f / HID) - mx * mx + 1e-5f);

    float dacc = 0.f;
#pragma unroll
    for (int j = 0; j < 8; j++) {
        int dd = tid + 256 * j;
        float ky = (kp[j] - mk) * rk * lkg[dd] + lkb[dd];
        float qy = (xv[j] - mx) * rx * lqg[dd] + lqb[dd];
        dacc += ky * qy;
    }
#pragma unroll
    for (int o = 16; o; o >>= 1) dacc += __shfl_xor_sync(0xffffffffu, dacc, o);
    __syncthreads();
    if (lane == 0) red[0][wid] = dacc;
    __syncthreads();
    if (tid == 0) {
        float s = 0.f;
#pragma unroll
        for (int w = 0; w < 8; w++) s += red[0][w];
        s *= rsqrtf((float)HID);
        float a = fmaxf(fabsf(s), 1e-6f);
        float sgn = (s > 0.f) ? 1.f : ((s < 0.f) ? -1.f : 0.f);
        float z = sqrtf(a) * sgn;
        gG[t] = 1.f / (1.f + expf(-z));
    }
}

// =====================================================================
extern "C" void kernel_launch(void* const* d_in, const int* in_sizes, int n_in,
                              void* d_out, int out_size) {
    const float* x      = (const float*)d_in[0];
    const int*   hashes = (const int*)  d_in[1];
    const int*   offs   = (const int*)  d_in[2];
    const float* emb    = (const float*)d_in[3];
    const float* convw  = (const float*)d_in[4];
    const float* lncg   = (const float*)d_in[5];
    const float* lncb   = (const float*)d_in[6];
    const float* Wk     = (const float*)d_in[7];
    const float* Wv     = (const float*)d_in[8];
    const float* Wo     = (const float*)d_in[9];
    const float* lkg    = (const float*)d_in[10];
    const float* lkb    = (const float*)d_in[11];
    const float* lqg    = (const float*)d_in[12];
    const float* lqb    = (const float*)d_in[13];
    float* out = (float*)d_out;

    // 0) M = Wo @ Wv (exact fp32; keeps value path at one tf32 rounding stage)
    k_matM<<<dim3(ED / 64, HID / 64), 256>>>(Wo, Wv);

    // 1) gather + conv + LN + SiLU -> gE
    k_embed<<<dim3(TT / 32, BB), 256>>>(hashes, offs, emb, convw, lncg, lncb);

    // 2) gKP = gE @ Wk^T   (tf32 tensor cores)
    k_gemm_tc<0><<<dim3(HID / 128, BT / 128), 256>>>(Wk, nullptr);

    // 3) gate
    k_gate<<<BT, 256>>>(x, lkg, lkb, lqg, lqb);

    // 4) out = diag(g) * (gE @ M^T)   (tf32 tensor cores)
    k_gemm_tc<1><<<dim3(HID / 128, BT / 128), 256>>>(nullptr, out);
}

// round 5
// speedup vs baseline: 2.3448x; 1.0352x over previous
#include <cuda_runtime.h>
#include <cuda_bf16.h>
#include <math.h>
#include <stdint.h>

// ---------------- problem constants ----------------
#define BB   4
#define TT   4096
#define BT   (BB*TT)      // 16384 tokens
#define HID  2048
#define ED   256          // engram dim
#define NH   8            // total hash heads
#define HD   32           // head dim
#define KW   4            // conv kernel
#define DILN 3            // dilation
#define PADL 9            // causal left pad

// ---------------- scratch (device globals; no allocation) ----------------
__device__ float  gE   [(size_t)BT * ED];        // e' tf32-rounded (16 MB)
__device__ float  gM   [(size_t)HID * ED];       // M = Wo@Wv, tf32-rounded (2 MB)
__device__ float  gWk32[(size_t)HID * ED];       // Wk tf32-rounded (2 MB)
__device__ float  gG   [BT];                     // per-token gate
__device__ float2 gXs  [BT];                     // per-token (mean, rstd) of x
__device__ float  gPart[(size_t)BT * 16 * 8];    // gate partials [row][colblk][8] (16 MB)

// ---------------- packed f32x2 helpers (exact-fp32 k_matM) --------------
typedef unsigned long long ull;
__device__ __forceinline__ ull pk2(float lo, float hi) {
    ull r; asm("mov.b64 %0, {%1, %2};" : "=l"(r) : "f"(lo), "f"(hi)); return r;
}
__device__ __forceinline__ void upk2(ull v, float& lo, float& hi) {
    asm("mov.b64 {%0, %1}, %2;" : "=f"(lo), "=f"(hi) : "l"(v));
}
__device__ __forceinline__ void fma2(ull& d, ull a, ull b) {
    asm("fma.rn.f32x2 %0, %1, %2, %0;" : "+l"(d) : "l"(a), "l"(b));
}

// ---------------- tf32 / ldmatrix / mma / cp.async helpers --------------
__device__ __forceinline__ uint32_t f2tf32(float f) {
    uint32_t u; asm("cvt.rna.tf32.f32 %0, %1;" : "=r"(u) : "f"(f)); return u;
}
__device__ __forceinline__ float tf32f(float f) { return __uint_as_float(f2tf32(f)); }
__device__ __forceinline__ uint32_t smem_u32(const void* p) {
    uint32_t r;
    asm("{ .reg .u64 t; cvta.to.shared.u64 t, %1; cvt.u32.u64 %0, t; }" : "=r"(r) : "l"(p));
    return r;
}
__device__ __forceinline__ void ldsm4(uint32_t& r0, uint32_t& r1, uint32_t& r2, uint32_t& r3,
                                      uint32_t addr) {
    asm volatile("ldmatrix.sync.aligned.m8n8.x4.shared.b16 {%0,%1,%2,%3}, [%4];"
                 : "=r"(r0), "=r"(r1), "=r"(r2), "=r"(r3) : "r"(addr));
}
__device__ __forceinline__ void mma_tf32(float* c, const uint32_t* a, uint32_t b0, uint32_t b1) {
    asm volatile("mma.sync.aligned.m16n8k8.row.col.f32.tf32.tf32.f32 "
                 "{%0,%1,%2,%3}, {%4,%5,%6,%7}, {%8,%9}, {%0,%1,%2,%3};"
                 : "+f"(c[0]), "+f"(c[1]), "+f"(c[2]), "+f"(c[3])
                 : "r"(a[0]), "r"(a[1]), "r"(a[2]), "r"(a[3]), "r"(b0), "r"(b1));
}
__device__ __forceinline__ void cpa16(uint32_t dst, const void* src) {
    asm volatile("cp.async.ca.shared.global [%0], [%1], 16;" :: "r"(dst), "l"(src));
}
__device__ __forceinline__ void cpa_commit() { asm volatile("cp.async.commit_group;"); }

// =====================================================================
// Kernel 0: gM[e,c] = sum_d Wo[e,d] * Wv[d,c]  (exact fp32, tf32-rounded store)
// =====================================================================
__global__ __launch_bounds__(256) void k_matM(const float* __restrict__ Wo,
                                              const float* __restrict__ Wv) {
    const int BM = 64, BN = 64, BK = 16, KT = 2048, NC = 256;
    __shared__ float As[BK][BM + 4];
    __shared__ float Bs[BK][BN + 4];

    int bm = blockIdx.y * BM, bn = blockIdx.x * BN;
    int tid = threadIdx.x;
    int tx = tid & 15, ty = tid >> 4;
    int m0 = ty * 4, n0 = tx * 4;

    ull acc[2][4];
#pragma unroll
    for (int i = 0; i < 2; i++)
#pragma unroll
        for (int j = 0; j < 4; j++) acc[i][j] = 0ull;

    for (int kt = 0; kt < KT; kt += BK) {
        {
            int m = tid >> 2, kq = tid & 3;
            float4 v = *(const float4*)(Wo + (size_t)(bm + m) * KT + kt + kq * 4);
            As[kq * 4 + 0][m] = v.x; As[kq * 4 + 1][m] = v.y;
            As[kq * 4 + 2][m] = v.z; As[kq * 4 + 3][m] = v.w;
        }
        {
            int kk = tid >> 4, nq = tid & 15;
            float4 v = *(const float4*)(Wv + (size_t)(kt + kk) * NC + bn + nq * 4);
            *(float4*)&Bs[kk][nq * 4] = v;
        }
        __syncthreads();
#pragma unroll
        for (int k = 0; k < BK; k++) {
            ull a2[2];
#pragma unroll
            for (int ip = 0; ip < 2; ip++) a2[ip] = *(const ull*)&As[k][m0 + 2 * ip];
            float4 b = *(const float4*)&Bs[k][n0];
            ull b2[4] = { pk2(b.x, b.x), pk2(b.y, b.y), pk2(b.z, b.z), pk2(b.w, b.w) };
#pragma unroll
            for (int ip = 0; ip < 2; ip++)
#pragma unroll
                for (int j = 0; j < 4; j++) fma2(acc[ip][j], a2[ip], b2[j]);
        }
        __syncthreads();
    }
#pragma unroll
    for (int ip = 0; ip < 2; ip++) {
        int r0 = bm + m0 + 2 * ip;
        float lo[4], hi[4];
#pragma unroll
        for (int j = 0; j < 4; j++) upk2(acc[ip][j], lo[j], hi[j]);
        float* d0 = gM + (size_t)r0 * NC + bn + n0;
        float* d1 = gM + (size_t)(r0 + 1) * NC + bn + n0;
#pragma unroll
        for (int j = 0; j < 4; j++) { d0[j] = tf32f(lo[j]); d1[j] = tf32f(hi[j]); }
    }
}

// =====================================================================
// Kernel 0b: tf32-convert Wk  (2048x256)
// =====================================================================
__global__ __launch_bounds__(256) void k_cvtWk(const float* __restrict__ Wk) {
    int i = (blockIdx.x * 256 + threadIdx.x) * 4;
    float4 v = *(const float4*)(Wk + i);
    float4 o = make_float4(tf32f(v.x), tf32f(v.y), tf32f(v.z), tf32f(v.w));
    *(float4*)(gWk32 + i) = o;
}

// =====================================================================
// Kernel 1: hash-gather + dilated causal depthwise conv + LN + SiLU -> gE (tf32)
// =====================================================================
__global__ __launch_bounds__(256) void k_embed(const int* __restrict__ hashes,
                                               const int* __restrict__ offs,
                                               const float* __restrict__ emb,
                                               const float* __restrict__ cw,
                                               const float* __restrict__ lg,
                                               const float* __restrict__ lb) {
    const int TB = 32, HALO = PADL;
    __shared__ float se[(TB + HALO) * ED];
    __shared__ float swt[KW * ED];
    __shared__ float sg[ED], sb[ED];

    int tid = threadIdx.x;
    int b = blockIdx.y, t0 = blockIdx.x * TB;

    sg[tid] = lg[tid];
    sb[tid] = lb[tid];
#pragma unroll
    for (int k = 0; k < KW; k++) swt[k * ED + tid] = cw[tid * KW + k];

    int h = tid >> 5, d = tid & 31;
    int off_h = offs[h];
    for (int lt = 0; lt < TB + HALO; lt++) {
        int t = t0 - HALO + lt;
        float v = 0.f;
        if (t >= 0) {
            int row = hashes[(b * TT + t) * NH + h] + off_h;
            v = emb[(size_t)row * HD + d];
        }
        se[lt * ED + tid] = v;
    }
    __syncthreads();

    int wid = tid >> 5, lane = tid & 31;
    for (int it = 0; it < TB / 8; it++) {
        int tok = it * 8 + wid;
        int lt = tok + HALO;
        float c[8], ev[8];
        float s = 0.f, q = 0.f;
#pragma unroll
        for (int j = 0; j < 8; j++) {
            int ch = lane + 32 * j;
            float a = 0.f;
#pragma unroll
            for (int k = 0; k < KW; k++)
                a += se[(lt - PADL + k * DILN) * ED + ch] * swt[k * ED + ch];
            c[j] = a;
            ev[j] = se[lt * ED + ch];
            s += a; q += a * a;
        }
#pragma unroll
        for (int o = 16; o; o >>= 1) {
            s += __shfl_xor_sync(0xffffffffu, s, o);
            q += __shfl_xor_sync(0xffffffffu, q, o);
        }
        float mean = s * (1.f / ED);
        float var  = q * (1.f / ED) - mean * mean;
        float rstd = rsqrtf(var + 1e-5f);
#pragma unroll
        for (int j = 0; j < 8; j++) {
            int ch = lane + 32 * j;
            float y = (c[j] - mean) * rstd * sg[ch] + sb[ch];
            float o = ev[j] + y * (1.f / (1.f + expf(-y)));
            gE[(size_t)(b * TT + t0 + tok) * ED + ch] = tf32f(o);
        }
    }
}

// =====================================================================
// Kernel 2: per-token mean/rstd of x  (warp per token)
// =====================================================================
__global__ __launch_bounds__(256) void k_xstats(const float* __restrict__ x) {
    int row = blockIdx.x * 8 + (threadIdx.x >> 5);
    int lane = threadIdx.x & 31;
    const float* xr = x + (size_t)row * HID;
    float s = 0.f, q = 0.f;
#pragma unroll
    for (int i = 0; i < 16; i++) {
        float4 v = *(const float4*)(xr + lane * 4 + i * 128);
        s += v.x + v.y + v.z + v.w;
        q += v.x * v.x + v.y * v.y + v.z * v.z + v.w * v.w;
    }
#pragma unroll
    for (int o = 16; o; o >>= 1) {
        s += __shfl_xor_sync(0xffffffffu, s, o);
        q += __shfl_xor_sync(0xffffffffu, q, o);
    }
    if (lane == 0) {
        float m = s * (1.f / HID);
        float var = q * (1.f / HID) - m * m;
        gXs[row] = make_float2(m, rsqrtf(var + 1e-5f));
    }
}

// =====================================================================
// Kernel 3/5: tf32 tensor GEMM NT, cp.async double-buffered.
//   C[BT x 2048] = gE[BT x 256] @ B[2048 x 256]^T
//   MODE 0: B = gWk32; epilogue computes gate partials (no C store).
//   MODE 1: B = gM;    epilogue scales rows by gG and stores to Cout.
//   Block 128x128, BK=32 (8 k-tiles), 8 warps (2m x 4n), warp tile 64x32.
//   Dynamic smem: As[2] + Bs[2], each 128*36 u32 -> 73728 B.
// =====================================================================
#define LDSW 36
#define BUFU (128 * LDSW)            // u32 per buffer

template <int MODE>
__global__ __launch_bounds__(256, 2) void k_gemm(float* __restrict__ Cout,
                                                 const float* __restrict__ x,
                                                 const float* __restrict__ lkg,
                                                 const float* __restrict__ lkb,
                                                 const float* __restrict__ lqg,
                                                 const float* __restrict__ lqb) {
    extern __shared__ uint32_t sh[];
    uint32_t* As = sh;               // [2][BUFU]
    uint32_t* Bs = sh + 2 * BUFU;    // [2][BUFU]

    const float* A  = gE;
    const float* Bp = (MODE == 0) ? gWk32 : gM;

    int bm = blockIdx.y * 128, bn = blockIdx.x * 128;
    int tid = threadIdx.x, lane = tid & 31, wid = tid >> 5;
    int wm = wid & 1, wn = wid >> 1;

    float acc[4][4][4];
#pragma unroll
    for (int mt = 0; mt < 4; mt++)
#pragma unroll
        for (int nt = 0; nt < 4; nt++)
#pragma unroll
            for (int r = 0; r < 4; r++) acc[mt][nt][r] = 0.f;

    uint32_t as0 = smem_u32(As), bs0 = smem_u32(Bs);
    uint32_t a_base = as0 + (((wm * 64 + (lane & 15)) * LDSW + ((lane >> 4) * 4)) << 2);
    uint32_t b_base = bs0 + (((wn * 32 + (lane >> 4) * 8 + (lane & 7)) * LDSW
                              + (((lane >> 3) & 1) * 4)) << 2);

    // tile issue: 4 x 16B per thread per operand
    auto issue = [&](int buf, int kt) {
        uint32_t ao = as0 + buf * (BUFU * 4);
        uint32_t bo = bs0 + buf * (BUFU * 4);
#pragma unroll
        for (int i = 0; i < 4; i++) {
            int idx = tid + 256 * i;
            int row = idx >> 3, q = idx & 7;
            cpa16(ao + ((row * LDSW + q * 4) << 2), A  + (size_t)(bm + row) * ED + kt + q * 4);
            cpa16(bo + ((row * LDSW + q * 4) << 2), Bp + (size_t)(bn + row) * ED + kt + q * 4);
        }
        cpa_commit();
    };

    issue(0, 0);
    for (int t = 0; t < 8; t++) {
        int buf = t & 1;
        if (t < 7) {
            issue(buf ^ 1, (t + 1) * 32);
            asm volatile("cp.async.wait_group 1;");
        } else {
            asm volatile("cp.async.wait_group 0;");
        }
        __syncthreads();
        uint32_t abuf = a_base + buf * (BUFU * 4);
        uint32_t bbuf = b_base + buf * (BUFU * 4);
#pragma unroll
        for (int ks = 0; ks < 4; ks++) {
            uint32_t a[4][4], b[2][4];
#pragma unroll
            for (int mt = 0; mt < 4; mt++)
                ldsm4(a[mt][0], a[mt][1], a[mt][2], a[mt][3],
                      abuf + ((mt * 16 * LDSW + ks * 8) << 2));
#pragma unroll
            for (int p = 0; p < 2; p++)
                ldsm4(b[p][0], b[p][1], b[p][2], b[p][3],
                      bbuf + ((p * 16 * LDSW + ks * 8) << 2));
#pragma unroll
            for (int mt = 0; mt < 4; mt++)
#pragma unroll
                for (int nt = 0; nt < 4; nt++) {
                    int p = nt >> 1, s = (nt & 1) * 2;
                    mma_tf32(acc[mt][nt], a[mt], b[p][s], b[p][s + 1]);
                }
        }
        __syncthreads();
    }

    if (MODE == 1) {
        // scale rows by gate, store
#pragma unroll
        for (int mt = 0; mt < 4; mt++) {
            int r0 = bm + wm * 64 + mt * 16 + (lane >> 2);
            float s0 = gG[r0], s1 = gG[r0 + 8];
#pragma unroll
            for (int nt = 0; nt < 4; nt++) {
                int c0 = bn + wn * 32 + nt * 8 + (lane & 3) * 2;
                *(float2*)(Cout + (size_t)r0 * HID + c0) =
                    make_float2(acc[mt][nt][0] * s0, acc[mt][nt][1] * s0);
                *(float2*)(Cout + (size_t)(r0 + 8) * HID + c0) =
                    make_float2(acc[mt][nt][2] * s1, acc[mt][nt][3] * s1);
            }
        }
    } else {
        // gate partials over this block's 128 columns:
        // p0=Σ KP·lkg·q, p1=Σ lkg·q, p2=Σ KP, p3=Σ KP², p4=Σ lkb·q
        float* sRed = (float*)sh;    // [4 wn][128 row][5]
#pragma unroll
        for (int mt = 0; mt < 4; mt++) {
#pragma unroll
            for (int half = 0; half < 2; half++) {
                int rl = wm * 64 + mt * 16 + half * 8 + (lane >> 2);
                int row = bm + rl;
                float2 xs = gXs[row];
                float mx = xs.x, rx = xs.y;
                float p0 = 0.f, p1 = 0.f, p2 = 0.f, p3 = 0.f, p4 = 0.f;
#pragma unroll
                for (int nt = 0; nt < 4; nt++) {
#pragma unroll
                    for (int e = 0; e < 2; e++) {
                        int col = bn + wn * 32 + nt * 8 + (lane & 3) * 2 + e;
                        float kp = acc[mt][nt][half * 2 + e];
                        float qv = (x[(size_t)row * HID + col] - mx) * rx * lqg[col] + lqb[col];
                        float lgq = lkg[col] * qv;
                        p0 += kp * lgq;
                        p1 += lgq;
                        p2 += kp;
                        p3 += kp * kp;
                        p4 += lkb[col] * qv;
                    }
                }
#pragma unroll
                for (int o = 1; o <= 2; o <<= 1) {
                    p0 += __shfl_xor_sync(0xffffffffu, p0, o);
                    p1 += __shfl_xor_sync(0xffffffffu, p1, o);
                    p2 += __shfl_xor_sync(0xffffffffu, p2, o);
                    p3 += __shfl_xor_sync(0xffffffffu, p3, o);
                    p4 += __shfl_xor_sync(0xffffffffu, p4, o);
                }
                if ((lane & 3) == 0) {
                    float* d = sRed + ((size_t)wn * 128 + rl) * 5;
                    d[0] = p0; d[1] = p1; d[2] = p2; d[3] = p3; d[4] = p4;
                }
            }
        }
        __syncthreads();
        for (int idx = tid; idx < 128 * 5; idx += 256) {
            int rl = idx / 5, j = idx - rl * 5;
            float s = sRed[((size_t)0 * 128 + rl) * 5 + j]
                    + sRed[((size_t)1 * 128 + rl) * 5 + j]
                    + sRed[((size_t)2 * 128 + rl) * 5 + j]
                    + sRed[((size_t)3 * 128 + rl) * 5 + j];
            gPart[(((size_t)(bm + rl)) * 16 + blockIdx.x) * 8 + j] = s;
        }
    }
}

// =====================================================================
// Kernel 4: finalize gate   dot = rk·S0 − rk·mk·S1 + S4
// =====================================================================
__global__ __launch_bounds__(256) void k_gfin() {
    int row = blockIdx.x * 256 + threadIdx.x;
    float S0 = 0.f, S1 = 0.f, S2 = 0.f, S3 = 0.f, S4 = 0.f;
#pragma unroll
    for (int nb = 0; nb < 16; nb++) {
        const float* p = gPart + (((size_t)row) * 16 + nb) * 8;
        S0 += p[0]; S1 += p[1]; S2 += p[2]; S3 += p[3]; S4 += p[4];
    }
    float mk = S2 * (1.f / HID);
    float rk = rsqrtf(S3 * (1.f / HID) - mk * mk + 1e-5f);
    float dot = rk * S0 - rk * mk * S1 + S4;
    float s = dot * rsqrtf((float)HID);
    float a = fmaxf(fabsf(s), 1e-6f);
    float sgn = (s > 0.f) ? 1.f : ((s < 0.f) ? -1.f : 0.f);
    gG[row] = 1.f / (1.f + expf(-sqrtf(a) * sgn));
}

// =====================================================================
extern "C" void kernel_launch(void* const* d_in, const int* in_sizes, int n_in,
                              void* d_out, int out_size) {
    const float* x      = (const float*)d_in[0];
    const int*   hashes = (const int*)  d_in[1];
    const int*   offs   = (const int*)  d_in[2];
    const float* emb    = (const float*)d_in[3];
    const float* convw  = (const float*)d_in[4];
    const float* lncg   = (const float*)d_in[5];
    const float* lncb   = (const float*)d_in[6];
    const float* Wk     = (const float*)d_in[7];
    const float* Wv     = (const float*)d_in[8];
    const float* Wo     = (const float*)d_in[9];
    const float* lkg    = (const float*)d_in[10];
    const float* lkb    = (const float*)d_in[11];
    const float* lqg    = (const float*)d_in[12];
    const float* lqb    = (const float*)d_in[13];
    float* out = (float*)d_out;

    const int GSM = 4 * BUFU * 4;    // 73728 B dynamic smem
    cudaFuncSetAttribute(k_gemm<0>, cudaFuncAttributeMaxDynamicSharedMemorySize, GSM);
    cudaFuncSetAttribute(k_gemm<1>, cudaFuncAttributeMaxDynamicSharedMemorySize, GSM);

    // 0) M = Wo @ Wv (exact fp32 -> tf32 store);  Wk -> tf32
    k_matM<<<dim3(ED / 64, HID / 64), 256>>>(Wo, Wv);
    k_cvtWk<<<HID * ED / 1024, 256>>>(Wk);

    // 1) gather + conv + LN + SiLU -> gE (tf32)
    k_embed<<<dim3(TT / 32, BB), 256>>>(hashes, offs, emb, convw, lncg, lncb);

    // 2) x row stats
    k_xstats<<<BT / 8, 256>>>(x);

    // 3) KP GEMM with fused gate partials (no KP materialization)
    k_gemm<0><<<dim3(HID / 128, BT / 128), 256, GSM>>>(nullptr, x, lkg, lkb, lqg, lqb);

    // 4) finalize gate
    k_gfin<<<BT / 256, 256>>>();

    // 5) out = diag(g) * (gE @ M^T)
    k_gemm<1><<<dim3(HID / 128, BT / 128), 256, GSM>>>(out, x, lkg, lkb, lqg, lqb);
}

// round 8
// speedup vs baseline: 2.9962x; 1.2778x over previous
#include <cuda_runtime.h>
#include <cuda_fp16.h>
#include <math.h>
#include <stdint.h>

// ---------------- problem constants ----------------
#define BB   4
#define TT   4096
#define BT   (BB*TT)      // 16384 tokens
#define HID  2048
#define ED   256          // engram dim
#define NH   8            // total hash heads
#define HD   32           // head dim
#define KW   4            // conv kernel
#define DILN 3            // dilation
#define PADL 9            // causal left pad

// ---------------- scratch (device globals; no allocation) ----------------
__device__ __align__(16) __half gEh [(size_t)BT * ED];    // e' fp16 (8 MB)
__device__ __align__(16) __half gMh [(size_t)HID * ED];   // M = Wo@Wv fp16 (1 MB)
__device__ __align__(16) __half gWkh[(size_t)HID * ED];   // Wk fp16 (1 MB)
__device__ float  gG   [BT];                              // per-token gate
__device__ float2 gXs  [BT];                              // per-token (mean, rstd) of x
__device__ float  gPart[(size_t)BT * 16 * 8];             // gate partials [row][colblk][8]

// ---------------- packed f32x2 helpers (exact-fp32 k_matM) --------------
typedef unsigned long long ull;
__device__ __forceinline__ ull pk2(float lo, float hi) {
    ull r; asm("mov.b64 %0, {%1, %2};" : "=l"(r) : "f"(lo), "f"(hi)); return r;
}
__device__ __forceinline__ void upk2(ull v, float& lo, float& hi) {
    asm("mov.b64 {%0, %1}, %2;" : "=f"(lo), "=f"(hi) : "l"(v));
}
__device__ __forceinline__ void fma2(ull& d, ull a, ull b) {
    asm("fma.rn.f32x2 %0, %1, %2, %0;" : "+l"(d) : "l"(a), "l"(b));
}

// ---------------- ldmatrix / mma / cp.async helpers ---------------------
__device__ __forceinline__ uint32_t smem_u32(const void* p) {
    uint32_t r;
    asm("{ .reg .u64 t; cvta.to.shared.u64 t, %1; cvt.u32.u64 %0, t; }" : "=r"(r) : "l"(p));
    return r;
}
__device__ __forceinline__ void ldsm4(uint32_t& r0, uint32_t& r1, uint32_t& r2, uint32_t& r3,
                                      uint32_t addr) {
    asm volatile("ldmatrix.sync.aligned.m8n8.x4.shared.b16 {%0,%1,%2,%3}, [%4];"
                 : "=r"(r0), "=r"(r1), "=r"(r2), "=r"(r3) : "r"(addr));
}
__device__ __forceinline__ void mma_f16(float* c, const uint32_t* a, uint32_t b0, uint32_t b1) {
    asm volatile("mma.sync.aligned.m16n8k16.row.col.f32.f16.f16.f32 "
                 "{%0,%1,%2,%3}, {%4,%5,%6,%7}, {%8,%9}, {%0,%1,%2,%3};"
                 : "+f"(c[0]), "+f"(c[1]), "+f"(c[2]), "+f"(c[3])
                 : "r"(a[0]), "r"(a[1]), "r"(a[2]), "r"(a[3]), "r"(b0), "r"(b1));
}
__device__ __forceinline__ void cpa16(uint32_t dst, const void* src) {
    asm volatile("cp.async.ca.shared.global [%0], [%1], 16;" :: "r"(dst), "l"(src));
}
__device__ __forceinline__ void cpa_commit() { asm volatile("cp.async.commit_group;"); }
template <int N> __device__ __forceinline__ void cpa_wait() {
    asm volatile("cp.async.wait_group %0;" :: "n"(N) : "memory");
}

// =====================================================================
// Kernel 0: gM = Wo @ Wv  (exact fp32 accumulate, fp16 store)
// =====================================================================
__global__ __launch_bounds__(256) void k_matM(const float* __restrict__ Wo,
                                              const float* __restrict__ Wv) {
    const int BM = 64, BN = 64, BK = 16, KT = 2048, NC = 256;
    __shared__ float As[BK][BM + 4];
    __shared__ float Bs[BK][BN + 4];

    int bm = blockIdx.y * BM, bn = blockIdx.x * BN;
    int tid = threadIdx.x;
    int tx = tid & 15, ty = tid >> 4;
    int m0 = ty * 4, n0 = tx * 4;

    ull acc[2][4];
#pragma unroll
    for (int i = 0; i < 2; i++)
#pragma unroll
        for (int j = 0; j < 4; j++) acc[i][j] = 0ull;

    for (int kt = 0; kt < KT; kt += BK) {
        {
            int m = tid >> 2, kq = tid & 3;
            float4 v = *(const float4*)(Wo + (size_t)(bm + m) * KT + kt + kq * 4);
            As[kq * 4 + 0][m] = v.x; As[kq * 4 + 1][m] = v.y;
            As[kq * 4 + 2][m] = v.z; As[kq * 4 + 3][m] = v.w;
        }
        {
            int kk = tid >> 4, nq = tid & 15;
            float4 v = *(const float4*)(Wv + (size_t)(kt + kk) * NC + bn + nq * 4);
            *(float4*)&Bs[kk][nq * 4] = v;
        }
        __syncthreads();
#pragma unroll
        for (int k = 0; k < BK; k++) {
            ull a2[2];
#pragma unroll
            for (int ip = 0; ip < 2; ip++) a2[ip] = *(const ull*)&As[k][m0 + 2 * ip];
            float4 b = *(const float4*)&Bs[k][n0];
            ull b2[4] = { pk2(b.x, b.x), pk2(b.y, b.y), pk2(b.z, b.z), pk2(b.w, b.w) };
#pragma unroll
            for (int ip = 0; ip < 2; ip++)
#pragma unroll
                for (int j = 0; j < 4; j++) fma2(acc[ip][j], a2[ip], b2[j]);
        }
        __syncthreads();
    }
#pragma unroll
    for (int ip = 0; ip < 2; ip++) {
        int r0 = bm + m0 + 2 * ip;
        float lo[4], hi[4];
#pragma unroll
        for (int j = 0; j < 4; j++) upk2(acc[ip][j], lo[j], hi[j]);
        __half* d0 = gMh + (size_t)r0 * NC + bn + n0;
        __half* d1 = gMh + (size_t)(r0 + 1) * NC + bn + n0;
#pragma unroll
        for (int j = 0; j < 4; j++) {
            d0[j] = __float2half_rn(lo[j]);
            d1[j] = __float2half_rn(hi[j]);
        }
    }
}

// =====================================================================
// Kernel 0b: fp16-convert Wk
// =====================================================================
__global__ __launch_bounds__(256) void k_cvtWk(const float* __restrict__ Wk) {
    int i = (blockIdx.x * 256 + threadIdx.x) * 4;
    float4 v = *(const float4*)(Wk + i);
    __half2 h0 = __floats2half2_rn(v.x, v.y);
    __half2 h1 = __floats2half2_rn(v.z, v.w);
    *(__half2*)(gWkh + i)     = h0;
    *(__half2*)(gWkh + i + 2) = h1;
}

// =====================================================================
// Kernel 1: hash-gather + dilated causal depthwise conv + LN + SiLU -> gEh
// =====================================================================
__global__ __launch_bounds__(256) void k_embed(const int* __restrict__ hashes,
                                               const int* __restrict__ offs,
                                               const float* __restrict__ emb,
                                               const float* __restrict__ cw,
                                               const float* __restrict__ lg,
                                               const float* __restrict__ lb) {
    const int TB = 32, HALO = PADL;
    __shared__ float se[(TB + HALO) * ED];
    __shared__ float swt[KW * ED];
    __shared__ float sg[ED], sb[ED];

    int tid = threadIdx.x;
    int b = blockIdx.y, t0 = blockIdx.x * TB;

    sg[tid] = lg[tid];
    sb[tid] = lb[tid];
#pragma unroll
    for (int k = 0; k < KW; k++) swt[k * ED + tid] = cw[tid * KW + k];

    int h = tid >> 5, d = tid & 31;
    int off_h = offs[h];
    for (int lt = 0; lt < TB + HALO; lt++) {
        int t = t0 - HALO + lt;
        float v = 0.f;
        if (t >= 0) {
            int row = hashes[(b * TT + t) * NH + h] + off_h;
            v = emb[(size_t)row * HD + d];
        }
        se[lt * ED + tid] = v;
    }
    __syncthreads();

    int wid = tid >> 5, lane = tid & 31;
    for (int it = 0; it < TB / 8; it++) {
        int tok = it * 8 + wid;
        int lt = tok + HALO;
        float c[8], ev[8];
        float s = 0.f, q = 0.f;
#pragma unroll
        for (int j = 0; j < 8; j++) {
            int ch = lane + 32 * j;
            float a = 0.f;
#pragma unroll
            for (int k = 0; k < KW; k++)
                a += se[(lt - PADL + k * DILN) * ED + ch] * swt[k * ED + ch];
            c[j] = a;
            ev[j] = se[lt * ED + ch];
            s += a; q += a * a;
        }
#pragma unroll
        for (int o = 16; o; o >>= 1) {
            s += __shfl_xor_sync(0xffffffffu, s, o);
            q += __shfl_xor_sync(0xffffffffu, q, o);
        }
        float mean = s * (1.f / ED);
        float var  = q * (1.f / ED) - mean * mean;
        float rstd = rsqrtf(var + 1e-5f);
#pragma unroll
        for (int j = 0; j < 8; j++) {
            int ch = lane + 32 * j;
            float y = (c[j] - mean) * rstd * sg[ch] + sb[ch];
            float o = ev[j] + y * (1.f / (1.f + expf(-y)));
            gEh[(size_t)(b * TT + t0 + tok) * ED + ch] = __float2half_rn(o);
        }
    }
}

// =====================================================================
// Kernel 2: per-token mean/rstd of x
// =====================================================================
__global__ __launch_bounds__(256) void k_xstats(const float* __restrict__ x) {
    int row = blockIdx.x * 8 + (threadIdx.x >> 5);
    int lane = threadIdx.x & 31;
    const float* xr = x + (size_t)row * HID;
    float s = 0.f, q = 0.f;
#pragma unroll
    for (int i = 0; i < 16; i++) {
        float4 v = *(const float4*)(xr + lane * 4 + i * 128);
        s += v.x + v.y + v.z + v.w;
        q += v.x * v.x + v.y * v.y + v.z * v.z + v.w * v.w;
    }
#pragma unroll
    for (int o = 16; o; o >>= 1) {
        s += __shfl_xor_sync(0xffffffffu, s, o);
        q += __shfl_xor_sync(0xffffffffu, q, o);
    }
    if (lane == 0) {
        float m = s * (1.f / HID);
        float var = q * (1.f / HID) - m * m;
        gXs[row] = make_float2(m, rsqrtf(var + 1e-5f));
    }
}

// =====================================================================
// Kernel 3/5: fp16 tensor GEMM NT (mma.sync.m16n8k16), cp.async 2-stage.
//   C[BT x 2048] = gEh[BT x 256] @ B[2048 x 256]^T
//   MODE 0: B = gWkh; epilogue -> gate partials (no C store).
//   MODE 1: B = gMh;  epilogue scales rows by gG, stores C.
//   Block 128x128, BK=64 halfs (4 k16-steps), 8 warps (2m x 4n), warp 64x32.
//   smem rows: 72 halfs (144 B = 9x16B; conflict-free, 16B-aligned).
// =====================================================================
#define LDSH 72
#define HBUF (128 * LDSH)                // halfs per operand buffer

template <int MODE>
__global__ __launch_bounds__(256, 2) void k_gemm(float* __restrict__ Cout,
                                                 const float* __restrict__ x,
                                                 const float* __restrict__ lkg,
                                                 const float* __restrict__ lkb,
                                                 const float* __restrict__ lqg,
                                                 const float* __restrict__ lqb) {
    extern __shared__ __half sh[];
    __half* As = sh;                     // [2][HBUF]
    __half* Bs = sh + 2 * HBUF;          // [2][HBUF]

    const __half* A  = gEh;
    const __half* Bp = (MODE == 0) ? gWkh : gMh;

    int bm = blockIdx.y * 128, bn = blockIdx.x * 128;
    int tid = threadIdx.x, lane = tid & 31, wid = tid >> 5;
    int wm = wid & 1, wn = wid >> 1;

    float acc[4][4][4];
#pragma unroll
    for (int mt = 0; mt < 4; mt++)
#pragma unroll
        for (int nt = 0; nt < 4; nt++)
#pragma unroll
            for (int r = 0; r < 4; r++) acc[mt][nt][r] = 0.f;

    uint32_t as0 = smem_u32(As), bs0 = smem_u32(Bs);
    // A frag: rows = lane&15 (16 rows), k-half chunk = lane>>4 (8 halfs)
    uint32_t a_base = as0 + (((wm * 64 + (lane & 15)) * LDSH + (lane >> 4) * 8) << 1);
    // B frag: rows = (lane>>4)*8 + (lane&7), chunk = (lane>>3)&1
    uint32_t b_base = bs0 + (((wn * 32 + (lane >> 4) * 8 + (lane & 7)) * LDSH
                              + ((lane >> 3) & 1) * 8) << 1);

    // stage load: per operand 128 rows x 64 halfs = 1024 x 16B; 4 chunks/thread
    auto issue = [&](int t) {
        int s = t & 1;
        uint32_t ao = as0 + s * (HBUF * 2);
        uint32_t bo = bs0 + s * (HBUF * 2);
        int kt = t * 64;
#pragma unroll
        for (int i = 0; i < 4; i++) {
            int idx = tid + 256 * i;
            int row = idx >> 3, q = idx & 7;
            cpa16(ao + ((row * LDSH + q * 8) << 1), A  + (size_t)(bm + row) * ED + kt + q * 8);
            cpa16(bo + ((row * LDSH + q * 8) << 1), Bp + (size_t)(bn + row) * ED + kt + q * 8);
        }
        cpa_commit();
    };

    issue(0);
    for (int t = 0; t < 4; t++) {                 // K = 256 / 64
        int s = t & 1;
        if (t < 3) { issue(t + 1); cpa_wait<1>(); }
        else       { cpa_wait<0>(); }
        __syncthreads();
        uint32_t abuf = a_base + s * (HBUF * 2);
        uint32_t bbuf = b_base + s * (HBUF * 2);
#pragma unroll
        for (int ks = 0; ks < 4; ks++) {          // 4 x k16
            uint32_t a[4][4], b[2][4];
#pragma unroll
            for (int mt = 0; mt < 4; mt++)
                ldsm4(a[mt][0], a[mt][1], a[mt][2], a[mt][3],
                      abuf + ((mt * 16 * LDSH + ks * 16) << 1));
#pragma unroll
            for (int p = 0; p < 2; p++)
                ldsm4(b[p][0], b[p][1], b[p][2], b[p][3],
                      bbuf + ((p * 16 * LDSH + ks * 16) << 1));
#pragma unroll
            for (int mt = 0; mt < 4; mt++)
#pragma unroll
                for (int nt = 0; nt < 4; nt++) {
                    int p = nt >> 1, q = (nt & 1) * 2;
                    mma_f16(acc[mt][nt], a[mt], b[p][q], b[p][q + 1]);
                }
        }
        __syncthreads();
    }

    if (MODE == 1) {
#pragma unroll
        for (int mt = 0; mt < 4; mt++) {
            int r0 = bm + wm * 64 + mt * 16 + (lane >> 2);
            float s0 = gG[r0], s1 = gG[r0 + 8];
#pragma unroll
            for (int nt = 0; nt < 4; nt++) {
                int c0 = bn + wn * 32 + nt * 8 + (lane & 3) * 2;
                *(float2*)(Cout + (size_t)r0 * HID + c0) =
                    make_float2(acc[mt][nt][0] * s0, acc[mt][nt][1] * s0);
                *(float2*)(Cout + (size_t)(r0 + 8) * HID + c0) =
                    make_float2(acc[mt][nt][2] * s1, acc[mt][nt][3] * s1);
            }
        }
    } else {
        // gate partials over this block's 128 cols:
        // p0=Σ KP·lkg·q, p1=Σ lkg·q, p2=Σ KP, p3=Σ KP², p4=Σ lkb·q
        float* sRed = (float*)sh;                 // [4 wn][128 row][5]; stages dead
#pragma unroll
        for (int mt = 0; mt < 4; mt++) {
#pragma unroll
            for (int half = 0; half < 2; half++) {
                int rl = wm * 64 + mt * 16 + half * 8 + (lane >> 2);
                int row = bm + rl;
                float2 xs = gXs[row];
                float mx = xs.x, rx = xs.y;
                float p0 = 0.f, p1 = 0.f, p2 = 0.f, p3 = 0.f, p4 = 0.f;
#pragma unroll
                for (int nt = 0; nt < 4; nt++) {
#pragma unroll
                    for (int e = 0; e < 2; e++) {
                        int col = bn + wn * 32 + nt * 8 + (lane & 3) * 2 + e;
                        float kp = acc[mt][nt][half * 2 + e];
                        float qv = (x[(size_t)row * HID + col] - mx) * rx * lqg[col] + lqb[col];
                        float lgq = lkg[col] * qv;
                        p0 += kp * lgq;
                        p1 += lgq;
                        p2 += kp;
                        p3 += kp * kp;
                        p4 += lkb[col] * qv;
                    }
                }
#pragma unroll
                for (int o = 1; o <= 2; o <<= 1) {
                    p0 += __shfl_xor_sync(0xffffffffu, p0, o);
                    p1 += __shfl_xor_sync(0xffffffffu, p1, o);
                    p2 += __shfl_xor_sync(0xffffffffu, p2, o);
                    p3 += __shfl_xor_sync(0xffffffffu, p3, o);
                    p4 += __shfl_xor_sync(0xffffffffu, p4, o);
                }
                if ((lane & 3) == 0) {
                    float* d = sRed + ((size_t)wn * 128 + rl) * 5;
                    d[0] = p0; d[1] = p1; d[2] = p2; d[3] = p3; d[4] = p4;
                }
            }
        }
        __syncthreads();
        for (int idx = tid; idx < 128 * 5; idx += 256) {
            int rl = idx / 5, j = idx - rl * 5;
            float s = sRed[((size_t)0 * 128 + rl) * 5 + j]
                    + sRed[((size_t)1 * 128 + rl) * 5 + j]
                    + sRed[((size_t)2 * 128 + rl) * 5 + j]
                    + sRed[((size_t)3 * 128 + rl) * 5 + j];
            gPart[(((size_t)(bm + rl)) * 16 + blockIdx.x) * 8 + j] = s;
        }
    }
}

// =====================================================================
// Kernel 4: finalize gate   dot = rk*S0 - rk*mk*S1 + S4
// =====================================================================
__global__ __launch_bounds__(256) void k_gfin() {
    int row = blockIdx.x * 256 + threadIdx.x;
    float S0 = 0.f, S1 = 0.f, S2 = 0.f, S3 = 0.f, S4 = 0.f;
#pragma unroll
    for (int nb = 0; nb < 16; nb++) {
        const float* p = gPart + (((size_t)row) * 16 + nb) * 8;
        S0 += p[0]; S1 += p[1]; S2 += p[2]; S3 += p[3]; S4 += p[4];
    }
    float mk = S2 * (1.f / HID);
    float rk = rsqrtf(S3 * (1.f / HID) - mk * mk + 1e-5f);
    float dot = rk * S0 - rk * mk * S1 + S4;
    float s = dot * rsqrtf((float)HID);
    float a = fmaxf(fabsf(s), 1e-6f);
    float sgn = (s > 0.f) ? 1.f : ((s < 0.f) ? -1.f : 0.f);
    gG[row] = 1.f / (1.f + expf(-sqrtf(a) * sgn));
}

// =====================================================================
extern "C" void kernel_launch(void* const* d_in, const int* in_sizes, int n_in,
                              void* d_out, int out_size) {
    const float* x      = (const float*)d_in[0];
    const int*   hashes = (const int*)  d_in[1];
    const int*   offs   = (const int*)  d_in[2];
    const float* emb    = (const float*)d_in[3];
    const float* convw  = (const float*)d_in[4];
    const float* lncg   = (const float*)d_in[5];
    const float* lncb   = (const float*)d_in[6];
    const float* Wk     = (const float*)d_in[7];
    const float* Wv     = (const float*)d_in[8];
    const float* Wo     = (const float*)d_in[9];
    const float* lkg    = (const float*)d_in[10];
    const float* lkb    = (const float*)d_in[11];
    const float* lqg    = (const float*)d_in[12];
    const float* lqb    = (const float*)d_in[13];
    float* out = (float*)d_out;

    const int GSM = 4 * HBUF * 2;        // 73728 B dynamic smem
    cudaFuncSetAttribute(k_gemm<0>, cudaFuncAttributeMaxDynamicSharedMemorySize, GSM);
    cudaFuncSetAttribute(k_gemm<1>, cudaFuncAttributeMaxDynamicSharedMemorySize, GSM);

    // 0) M = Wo @ Wv (exact fp32 -> fp16 store);  Wk -> fp16
    k_matM<<<dim3(ED / 64, HID / 64), 256>>>(Wo, Wv);
    k_cvtWk<<<HID * ED / 1024, 256>>>(Wk);

    // 1) gather + conv + LN + SiLU -> gEh (fp16)
    k_embed<<<dim3(TT / 32, BB), 256>>>(hashes, offs, emb, convw, lncg, lncb);

    // 2) x row stats
    k_xstats<<<BT / 8, 256>>>(x);

    // 3) KP GEMM (fp16 tensor cores) with fused gate partials
    k_gemm<0><<<dim3(HID / 128, BT / 128), 256, GSM>>>(nullptr, x, lkg, lkb, lqg, lqb);

    // 4) finalize gate
    k_gfin<<<BT / 256, 256>>>();

    // 5) out = diag(g) * (gEh @ M^T)  (fp16 tensor cores)
    k_gemm<1><<<dim3(HID / 128, BT / 128), 256, GSM>>>(out, x, lkg, lkb, lqg, lqb);
}

// round 9
// speedup vs baseline: 4.3493x; 1.4516x over previous
#include <cuda_runtime.h>
#include <cuda_fp16.h>
#include <math.h>
#include <stdint.h>

// ---------------- problem constants ----------------
#define BB   4
#define TT   4096
#define BT   (BB*TT)      // 16384 tokens
#define HID  2048
#define ED   256          // engram dim
#define NH   8            // total hash heads
#define HD   32           // head dim
#define KW   4            // conv kernel
#define DILN 3            // dilation
#define PADL 9            // causal left pad

// ---------------- scratch (device globals; no allocation) ----------------
__device__ __align__(16) __half gEh [(size_t)BT * ED];    // e' fp16 (8 MB)
__device__ __align__(16) __half gMh [(size_t)HID * ED];   // M = Wo@Wv fp16 (1 MB)
__device__ __align__(16) __half gWkh[(size_t)HID * ED];   // Wk fp16 (1 MB)
__device__ float  gG   [BT];                              // per-token gate
__device__ __align__(16) float gPart[(size_t)BT * 16 * 16]; // gate partials / matM split-K scratch
__device__ float4 gCst;                                   // (Sa, Sb, Sc, Sd)

// ---------------- helpers ----------------------------------------------
__device__ __forceinline__ uint32_t f2tf32(float f) {
    uint32_t u; asm("cvt.rna.tf32.f32 %0, %1;" : "=r"(u) : "f"(f)); return u;
}
__device__ __forceinline__ uint32_t smem_u32(const void* p) {
    uint32_t r;
    asm("{ .reg .u64 t; cvta.to.shared.u64 t, %1; cvt.u32.u64 %0, t; }" : "=r"(r) : "l"(p));
    return r;
}
__device__ __forceinline__ void ldsm4(uint32_t& r0, uint32_t& r1, uint32_t& r2, uint32_t& r3,
                                      uint32_t addr) {
    asm volatile("ldmatrix.sync.aligned.m8n8.x4.shared.b16 {%0,%1,%2,%3}, [%4];"
                 : "=r"(r0), "=r"(r1), "=r"(r2), "=r"(r3) : "r"(addr));
}
__device__ __forceinline__ void mma_f16(float* c, const uint32_t* a, uint32_t b0, uint32_t b1) {
    asm volatile("mma.sync.aligned.m16n8k16.row.col.f32.f16.f16.f32 "
                 "{%0,%1,%2,%3}, {%4,%5,%6,%7}, {%8,%9}, {%0,%1,%2,%3};"
                 : "+f"(c[0]), "+f"(c[1]), "+f"(c[2]), "+f"(c[3])
                 : "r"(a[0]), "r"(a[1]), "r"(a[2]), "r"(a[3]), "r"(b0), "r"(b1));
}
__device__ __forceinline__ void mma_tf32(float* c, const uint32_t* a, uint32_t b0, uint32_t b1) {
    asm volatile("mma.sync.aligned.m16n8k8.row.col.f32.tf32.tf32.f32 "
                 "{%0,%1,%2,%3}, {%4,%5,%6,%7}, {%8,%9}, {%0,%1,%2,%3};"
                 : "+f"(c[0]), "+f"(c[1]), "+f"(c[2]), "+f"(c[3])
                 : "r"(a[0]), "r"(a[1]), "r"(a[2]), "r"(a[3]), "r"(b0), "r"(b1));
}
__device__ __forceinline__ void cpa16(uint32_t dst, const void* src) {
    asm volatile("cp.async.ca.shared.global [%0], [%1], 16;" :: "r"(dst), "l"(src));
}
__device__ __forceinline__ void cpa_commit() { asm volatile("cp.async.commit_group;"); }
template <int N> __device__ __forceinline__ void cpa_wait() {
    asm volatile("cp.async.wait_group %0;" :: "n"(N) : "memory");
}

// =====================================================================
// Kernel 0: matM split-K  (tf32 tensor cores)
//   partial[kc] = Wo[:, kc*512:(kc+1)*512] @ Wv[kc*512:(kc+1)*512, :]
//   Block 128x64, BK=32, 8 warps (4m x 2n), warp tile 32x32. grid (4,16,4).
//   Partials (fp32) into gPart[kc * 2048*256 + e*256 + c].
// =====================================================================
#define MLDS 36
__global__ __launch_bounds__(256) void k_matM5(const float* __restrict__ Wo,
                                               const float* __restrict__ Wv) {
    __shared__ uint32_t As[128 * MLDS];   // 18.4 KB
    __shared__ uint32_t Bs[64 * MLDS];    //  9.2 KB
    int bn = blockIdx.x * 64;
    int bm = blockIdx.y * 128;
    int K0 = blockIdx.z * 512;
    int tid = threadIdx.x, lane = tid & 31, wid = tid >> 5;
    int wm = wid & 3, wn = wid >> 2;      // 4x2 warps, 32x32 each

    float acc[2][4][4];
#pragma unroll
    for (int mt = 0; mt < 2; mt++)
#pragma unroll
        for (int nt = 0; nt < 4; nt++)
#pragma unroll
            for (int r = 0; r < 4; r++) acc[mt][nt][r] = 0.f;

    uint32_t as0 = smem_u32(As), bs0 = smem_u32(Bs);
    uint32_t a_base = as0 + (((wm * 32 + (lane & 15)) * MLDS + (lane >> 4) * 4) << 2);
    uint32_t b_base = bs0 + (((wn * 32 + (lane >> 4) * 8 + (lane & 7)) * MLDS
                              + ((lane >> 3) & 1) * 4) << 2);

    for (int kt = 0; kt < 512; kt += 32) {
        // A: 128 rows x 32 k  (Wo row-major, K-contiguous)
#pragma unroll
        for (int i = 0; i < 4; i++) {
            int idx = tid + 256 * i;
            int r = idx >> 3, q = idx & 7;
            float4 v = *(const float4*)(Wo + (size_t)(bm + r) * 2048 + K0 + kt + q * 4);
            uint32_t* d = &As[r * MLDS + q * 4];
            d[0] = f2tf32(v.x); d[1] = f2tf32(v.y); d[2] = f2tf32(v.z); d[3] = f2tf32(v.w);
        }
        // B: 32 k x 64 c from Wv[k][c] -> transposed store Bs[c][k]
#pragma unroll
        for (int p = 0; p < 2; p++) {
            int kk = (tid >> 4) + p * 16;
            int c4 = (tid & 15) * 4;
            float4 v = *(const float4*)(Wv + (size_t)(K0 + kt + kk) * 256 + bn + c4);
            Bs[(c4 + 0) * MLDS + kk] = f2tf32(v.x);
            Bs[(c4 + 1) * MLDS + kk] = f2tf32(v.y);
            Bs[(c4 + 2) * MLDS + kk] = f2tf32(v.z);
            Bs[(c4 + 3) * MLDS + kk] = f2tf32(v.w);
        }
        __syncthreads();
#pragma unroll
        for (int ks = 0; ks < 4; ks++) {
            uint32_t a[2][4], b[2][4];
#pragma unroll
            for (int mt = 0; mt < 2; mt++)
                ldsm4(a[mt][0], a[mt][1], a[mt][2], a[mt][3],
                      a_base + ((mt * 16 * MLDS + ks * 8) << 2));
#pragma unroll
            for (int p = 0; p < 2; p++)
                ldsm4(b[p][0], b[p][1], b[p][2], b[p][3],
                      b_base + ((p * 16 * MLDS + ks * 8) << 2));
#pragma unroll
            for (int mt = 0; mt < 2; mt++)
#pragma unroll
                for (int nt = 0; nt < 4; nt++) {
                    int p = nt >> 1, s = (nt & 1) * 2;
                    mma_tf32(acc[mt][nt], a[mt], b[p][s], b[p][s + 1]);
                }
        }
        __syncthreads();
    }

    float* pm = gPart + (size_t)blockIdx.z * (2048 * 256);
#pragma unroll
    for (int mt = 0; mt < 2; mt++) {
        int r0 = bm + wm * 32 + mt * 16 + (lane >> 2);
#pragma unroll
        for (int nt = 0; nt < 4; nt++) {
            int c0 = bn + wn * 32 + nt * 8 + (lane & 3) * 2;
            *(float2*)(pm + (size_t)r0 * 256 + c0) =
                make_float2(acc[mt][nt][0], acc[mt][nt][1]);
            *(float2*)(pm + (size_t)(r0 + 8) * 256 + c0) =
                make_float2(acc[mt][nt][2], acc[mt][nt][3]);
        }
    }
}

// Reduce the 4 split-K partials -> fp16 gMh
__global__ __launch_bounds__(256) void k_matred() {
    int i = (blockIdx.x * 256 + threadIdx.x) * 4;
    float4 s = *(const float4*)(gPart + i);
#pragma unroll
    for (int kc = 1; kc < 4; kc++) {
        float4 v = *(const float4*)(gPart + (size_t)kc * (2048 * 256) + i);
        s.x += v.x; s.y += v.y; s.z += v.z; s.w += v.w;
    }
    *(__half2*)(gMh + i)     = __floats2half2_rn(s.x, s.y);
    *(__half2*)(gMh + i + 2) = __floats2half2_rn(s.z, s.w);
}

// =====================================================================
// Kernel 0b: fp16-convert Wk
// =====================================================================
__global__ __launch_bounds__(256) void k_cvtWk(const float* __restrict__ Wk) {
    int i = (blockIdx.x * 256 + threadIdx.x) * 4;
    float4 v = *(const float4*)(Wk + i);
    *(__half2*)(gWkh + i)     = __floats2half2_rn(v.x, v.y);
    *(__half2*)(gWkh + i + 2) = __floats2half2_rn(v.z, v.w);
}

// =====================================================================
// Kernel 0c: global LN-weight dot constants Sa..Sd (one block)
// =====================================================================
__global__ __launch_bounds__(256) void k_const(const float* __restrict__ lkg,
                                               const float* __restrict__ lkb,
                                               const float* __restrict__ lqg,
                                               const float* __restrict__ lqb) {
    __shared__ float red[4][8];
    int tid = threadIdx.x, lane = tid & 31, wid = tid >> 5;
    float sa = 0.f, sb = 0.f, sc = 0.f, sd = 0.f;
    for (int c = tid; c < HID; c += 256) {
        float g1 = lkg[c], b1 = lkb[c], q1 = lqg[c], q0 = lqb[c];
        sa += g1 * q1; sb += g1 * q0; sc += b1 * q1; sd += b1 * q0;
    }
#pragma unroll
    for (int o = 16; o; o >>= 1) {
        sa += __shfl_xor_sync(0xffffffffu, sa, o);
        sb += __shfl_xor_sync(0xffffffffu, sb, o);
        sc += __shfl_xor_sync(0xffffffffu, sc, o);
        sd += __shfl_xor_sync(0xffffffffu, sd, o);
    }
    if (lane == 0) { red[0][wid] = sa; red[1][wid] = sb; red[2][wid] = sc; red[3][wid] = sd; }
    __syncthreads();
    if (tid == 0) {
        float a = 0.f, b = 0.f, c = 0.f, d = 0.f;
#pragma unroll
        for (int w = 0; w < 8; w++) { a += red[0][w]; b += red[1][w]; c += red[2][w]; d += red[3][w]; }
        gCst = make_float4(a, b, c, d);
    }
}

// =====================================================================
// Kernel 1: hash-gather + dilated causal depthwise conv + LN + SiLU -> gEh
// =====================================================================
__global__ __launch_bounds__(256) void k_embed(const int* __restrict__ hashes,
                                               const int* __restrict__ offs,
                                               const float* __restrict__ emb,
                                               const float* __restrict__ cw,
                                               const float* __restrict__ lg,
                                               const float* __restrict__ lb) {
    const int TB = 32, HALO = PADL;
    __shared__ float se[(TB + HALO) * ED];
    __shared__ float swt[KW * ED];
    __shared__ float sg[ED], sb[ED];

    int tid = threadIdx.x;
    int b = blockIdx.y, t0 = blockIdx.x * TB;

    sg[tid] = lg[tid];
    sb[tid] = lb[tid];
#pragma unroll
    for (int k = 0; k < KW; k++) swt[k * ED + tid] = cw[tid * KW + k];

    int h = tid >> 5, d = tid & 31;
    int off_h = offs[h];
    for (int lt = 0; lt < TB + HALO; lt++) {
        int t = t0 - HALO + lt;
        float v = 0.f;
        if (t >= 0) {
            int row = hashes[(b * TT + t) * NH + h] + off_h;
            v = emb[(size_t)row * HD + d];
        }
        se[lt * ED + tid] = v;
    }
    __syncthreads();

    int wid = tid >> 5, lane = tid & 31;
    for (int it = 0; it < TB / 8; it++) {
        int tok = it * 8 + wid;
        int lt = tok + HALO;
        float c[8], ev[8];
        float s = 0.f, q = 0.f;
#pragma unroll
        for (int j = 0; j < 8; j++) {
            int ch = lane + 32 * j;
            float a = 0.f;
#pragma unroll
            for (int k = 0; k < KW; k++)
                a += se[(lt - PADL + k * DILN) * ED + ch] * swt[k * ED + ch];
            c[j] = a;
            ev[j] = se[lt * ED + ch];
            s += a; q += a * a;
        }
#pragma unroll
        for (int o = 16; o; o >>= 1) {
            s += __shfl_xor_sync(0xffffffffu, s, o);
            q += __shfl_xor_sync(0xffffffffu, q, o);
        }
        float mean = s * (1.f / ED);
        float var  = q * (1.f / ED) - mean * mean;
        float rstd = rsqrtf(var + 1e-5f);
#pragma unroll
        for (int j = 0; j < 8; j++) {
            int ch = lane + 32 * j;
            float y = (c[j] - mean) * rstd * sg[ch] + sb[ch];
            float o = ev[j] + y * (1.f / (1.f + expf(-y)));
            gEh[(size_t)(b * TT + t0 + tok) * ED + ch] = __float2half_rn(o);
        }
    }
}

// =====================================================================
// Kernel 3/5: fp16 tensor GEMM NT (mma.sync.m16n8k16), cp.async 2-stage.
//   MODE 0: B = gWkh; epilogue -> 9 raw gate partials (incl. x stats).
//   MODE 1: B = gMh;  epilogue scales rows by gG, stores C.
// =====================================================================
#define LDSH 72
#define HBUF (128 * LDSH)                // halfs per operand buffer

template <int MODE>
__global__ __launch_bounds__(256, 2) void k_gemm(float* __restrict__ Cout,
                                                 const float* __restrict__ x,
                                                 const float* __restrict__ lkg,
                                                 const float* __restrict__ lkb,
                                                 const float* __restrict__ lqg,
                                                 const float* __restrict__ lqb) {
    extern __shared__ __half sh[];
    __half* As = sh;                     // [2][HBUF]
    __half* Bs = sh + 2 * HBUF;          // [2][HBUF]

    const __half* A  = gEh;
    const __half* Bp = (MODE == 0) ? gWkh : gMh;

    int bm = blockIdx.y * 128, bn = blockIdx.x * 128;
    int tid = threadIdx.x, lane = tid & 31, wid = tid >> 5;
    int wm = wid & 1, wn = wid >> 1;

    float acc[4][4][4];
#pragma unroll
    for (int mt = 0; mt < 4; mt++)
#pragma unroll
        for (int nt = 0; nt < 4; nt++)
#pragma unroll
            for (int r = 0; r < 4; r++) acc[mt][nt][r] = 0.f;

    uint32_t as0 = smem_u32(As), bs0 = smem_u32(Bs);
    uint32_t a_base = as0 + (((wm * 64 + (lane & 15)) * LDSH + (lane >> 4) * 8) << 1);
    uint32_t b_base = bs0 + (((wn * 32 + (lane >> 4) * 8 + (lane & 7)) * LDSH
                              + ((lane >> 3) & 1) * 8) << 1);

    auto issue = [&](int t) {
        int s = t & 1;
        uint32_t ao = as0 + s * (HBUF * 2);
        uint32_t bo = bs0 + s * (HBUF * 2);
        int kt = t * 64;
#pragma unroll
        for (int i = 0; i < 4; i++) {
            int idx = tid + 256 * i;
            int row = idx >> 3, q = idx & 7;
            cpa16(ao + ((row * LDSH + q * 8) << 1), A  + (size_t)(bm + row) * ED + kt + q * 8);
            cpa16(bo + ((row * LDSH + q * 8) << 1), Bp + (size_t)(bn + row) * ED + kt + q * 8);
        }
        cpa_commit();
    };

    issue(0);
    for (int t = 0; t < 4; t++) {
        int s = t & 1;
        if (t < 3) { issue(t + 1); cpa_wait<1>(); }
        else       { cpa_wait<0>(); }
        __syncthreads();
        uint32_t abuf = a_base + s * (HBUF * 2);
        uint32_t bbuf = b_base + s * (HBUF * 2);
#pragma unroll
        for (int ks = 0; ks < 4; ks++) {
            uint32_t a[4][4], b[2][4];
#pragma unroll
            for (int mt = 0; mt < 4; mt++)
                ldsm4(a[mt][0], a[mt][1], a[mt][2], a[mt][3],
                      abuf + ((mt * 16 * LDSH + ks * 16) << 1));
#pragma unroll
            for (int p = 0; p < 2; p++)
                ldsm4(b[p][0], b[p][1], b[p][2], b[p][3],
                      bbuf + ((p * 16 * LDSH + ks * 16) << 1));
#pragma unroll
            for (int mt = 0; mt < 4; mt++)
#pragma unroll
                for (int nt = 0; nt < 4; nt++) {
                    int p = nt >> 1, q = (nt & 1) * 2;
                    mma_f16(acc[mt][nt], a[mt], b[p][q], b[p][q + 1]);
                }
        }
        __syncthreads();
    }

    if (MODE == 1) {
#pragma unroll
        for (int mt = 0; mt < 4; mt++) {
            int r0 = bm + wm * 64 + mt * 16 + (lane >> 2);
            float s0 = gG[r0], s1 = gG[r0 + 8];
#pragma unroll
            for (int nt = 0; nt < 4; nt++) {
                int c0 = bn + wn * 32 + nt * 8 + (lane & 3) * 2;
                *(float2*)(Cout + (size_t)r0 * HID + c0) =
                    make_float2(acc[mt][nt][0] * s0, acc[mt][nt][1] * s0);
                *(float2*)(Cout + (size_t)(r0 + 8) * HID + c0) =
                    make_float2(acc[mt][nt][2] * s1, acc[mt][nt][3] * s1);
            }
        }
    } else {
        // 9 raw partials: P1=Σkp·a·x  P2=Σkp·a  P3=Σa·x  P4=Σkp·b  P5=Σc·x
        //                 P6=Σkp  P7=Σkp²  P8=Σx  P9=Σx²   (a=lkg·lqg, b=lkg·lqb, c=lkb·lqg)
        float* sA   = (float*)sh;                 // [128] per-col a
        float* sB   = sA + 128;                   // [128] per-col b
        float* sC   = sB + 128;                   // [128] per-col c
        float* sRed = sC + 128;                   // [4][128][9]
        if (tid < 128) {
            int col = bn + tid;
            float g1 = lkg[col], q1 = lqg[col], b1 = lkb[col], q0 = lqb[col];
            sA[tid] = g1 * q1; sB[tid] = g1 * q0; sC[tid] = b1 * q1;
        }
        __syncthreads();
#pragma unroll
        for (int mt = 0; mt < 4; mt++) {
#pragma unroll
            for (int half = 0; half < 2; half++) {
                int rl = wm * 64 + mt * 16 + half * 8 + (lane >> 2);
                int row = bm + rl;
                float p[9];
#pragma unroll
                for (int j = 0; j < 9; j++) p[j] = 0.f;
#pragma unroll
                for (int nt = 0; nt < 4; nt++) {
#pragma unroll
                    for (int e = 0; e < 2; e++) {
                        int cl = wn * 32 + nt * 8 + (lane & 3) * 2 + e;
                        float kp = acc[mt][nt][half * 2 + e];
                        float xv = x[(size_t)row * HID + bn + cl];
                        float a = sA[cl], b = sB[cl], c = sC[cl];
                        float ax = a * xv;
                        p[0] += kp * ax;
                        p[1] += kp * a;
                        p[2] += ax;
                        p[3] += kp * b;
                        p[4] += c * xv;
                        p[5] += kp;
                        p[6] += kp * kp;
                        p[7] += xv;
                        p[8] += xv * xv;
                    }
                }
#pragma unroll
                for (int o = 1; o <= 2; o <<= 1)
#pragma unroll
                    for (int j = 0; j < 9; j++)
                        p[j] += __shfl_xor_sync(0xffffffffu, p[j], o);
                if ((lane & 3) == 0) {
                    float* d = sRed + ((size_t)wn * 128 + rl) * 9;
#pragma unroll
                    for (int j = 0; j < 9; j++) d[j] = p[j];
                }
            }
        }
        __syncthreads();
        for (int idx = tid; idx < 128 * 9; idx += 256) {
            int rl = idx / 9, j = idx - rl * 9;
            float s = sRed[((size_t)0 * 128 + rl) * 9 + j]
                    + sRed[((size_t)1 * 128 + rl) * 9 + j]
                    + sRed[((size_t)2 * 128 + rl) * 9 + j]
                    + sRed[((size_t)3 * 128 + rl) * 9 + j];
            gPart[(((size_t)(bm + rl)) * 16 + blockIdx.x) * 16 + j] = s;
        }
    }
}

// =====================================================================
// Kernel 4: finalize gate from 9 partials + global constants
// =====================================================================
__global__ __launch_bounds__(256) void k_gfin() {
    int row = blockIdx.x * 256 + threadIdx.x;
    float P[9];
#pragma unroll
    for (int j = 0; j < 9; j++) P[j] = 0.f;
#pragma unroll
    for (int nb = 0; nb < 16; nb++) {
        const float* p = gPart + (((size_t)row) * 16 + nb) * 16;
#pragma unroll
        for (int j = 0; j < 9; j++) P[j] += p[j];
    }
    float4 C = gCst;
    float mk = P[5] * (1.f / HID);
    float rk = rsqrtf(P[6] * (1.f / HID) - mk * mk + 1e-5f);
    float mx = P[7] * (1.f / HID);
    float rx = rsqrtf(P[8] * (1.f / HID) - mx * mx + 1e-5f);
    float dot = rk * rx * (P[0] - mx * P[1] - mk * P[2] + mk * mx * C.x)
              + rk * (P[3] - mk * C.y)
              + rx * (P[4] - mx * C.z)
              + C.w;
    float s = dot * rsqrtf((float)HID);
    float a = fmaxf(fabsf(s), 1e-6f);
    float sgn = (s > 0.f) ? 1.f : ((s < 0.f) ? -1.f : 0.f);
    gG[row] = 1.f / (1.f + expf(-sqrtf(a) * sgn));
}

// =====================================================================
extern "C" void kernel_launch(void* const* d_in, const int* in_sizes, int n_in,
                              void* d_out, int out_size) {
    const float* x      = (const float*)d_in[0];
    const int*   hashes = (const int*)  d_in[1];
    const int*   offs   = (const int*)  d_in[2];
    const float* emb    = (const float*)d_in[3];
    const float* convw  = (const float*)d_in[4];
    const float* lncg   = (const float*)d_in[5];
    const float* lncb   = (const float*)d_in[6];
    const float* Wk     = (const float*)d_in[7];
    const float* Wv     = (const float*)d_in[8];
    const float* Wo     = (const float*)d_in[9];
    const float* lkg    = (const float*)d_in[10];
    const float* lkb    = (const float*)d_in[11];
    const float* lqg    = (const float*)d_in[12];
    const float* lqb    = (const float*)d_in[13];
    float* out = (float*)d_out;

    const int GSM = 4 * HBUF * 2;        // 73728 B dynamic smem
    cudaFuncSetAttribute(k_gemm<0>, cudaFuncAttributeMaxDynamicSharedMemorySize, GSM);
    cudaFuncSetAttribute(k_gemm<1>, cudaFuncAttributeMaxDynamicSharedMemorySize, GSM);

    // 0) M = Wo @ Wv  (tf32 tensor cores, split-K=4) -> fp16 gMh
    k_matM5<<<dim3(4, 16, 4), 256>>>(Wo, Wv);
    k_matred<<<512, 256>>>();

    // 0b) Wk -> fp16; LN-weight constants
    k_cvtWk<<<HID * ED / 1024, 256>>>(Wk);
    k_const<<<1, 256>>>(lkg, lkb, lqg, lqb);

    // 1) gather + conv + LN + SiLU -> gEh
    k_embed<<<dim3(TT / 32, BB), 256>>>(hashes, offs, emb, convw, lncg, lncb);

    // 2) KP GEMM (fp16 tensor cores) with fused gate partials + x stats
    k_gemm<0><<<dim3(HID / 128, BT / 128), 256, GSM>>>(nullptr, x, lkg, lkb, lqg, lqb);

    // 3) finalize gate
    k_gfin<<<BT / 256, 256>>>();

    // 4) out = diag(g) * (gEh @ M^T)
    k_gemm<1><<<dim3(HID / 128, BT / 128), 256, GSM>>>(out, x, lkg, lkb, lqg, lqb);
}